// round 8
// baseline (speedup 1.0000x reference)
#include <cuda_runtime.h>
#include <mma.h>
#include <cstdint>
#include <cstddef>

using namespace nvcuda;

// Problem constants
#define kT 512
#define kB 64
#define kH 1024
#define kG 3072
#define kL 4

// Recurrence config: 64 CTAs x 16 warps (4 K-quarters x 4 batch-quarters).
#define HS 16
#define NR 48
#define NCTA 64
#define RTH 512
#define KITERS 128
#define GHS_LD 66
#define SA_FLOATS (3 * KITERS * 32 * 4)
#define REC_SMEM ((SA_FLOATS + 2 * NR * GHS_LD) * 4)   /* 221952 B */

// gi GEMM config: 128x128 CTA tile, 8 warps of 64x32, BK=16, double-buffered
#define GI_LDA 36
#define GI2_TH 256
#define GI2_SMEM (2 * 2 * 128 * GI_LDA * 4)   /* 73728 B */

// ---------------------------------------------------------------------------
// Scratch
// ---------------------------------------------------------------------------
__device__ float g_seqA[kT * kB * kH];
__device__ float g_seqB[kT * kB * kH];
__device__ float g_gi[(size_t)kT * kB * kG];
__device__ float g_hT[2 * kB * kH];
__device__ float g_xr[kT * kB * kH];           // tf32-rounded x
__device__ float g_wr[(size_t)kL * kG * kH];   // tf32-rounded w_ih
__device__ unsigned g_count;

__global__ void reset_bar_kernel() { g_count = 0u; }

// Grid barrier: release-add then acquire-poll on the same counter.
// Release orders this CTA's hT stores before the add; acquire on the final
// count makes all CTAs' stores visible (gpu-scope cumulativity).
__device__ __forceinline__ void grid_barrier(unsigned idx) {
  __syncthreads();
  if (threadIdx.x == 0) {
    unsigned* cnt = &g_count;
    unsigned target = (unsigned)NCTA * (idx + 1u);
    unsigned old;
    asm volatile("atom.release.gpu.global.add.u32 %0, [%1], 1;"
                 : "=r"(old) : "l"(cnt) : "memory");
    unsigned v;
    do {
      asm volatile("ld.acquire.gpu.global.u32 %0, [%1];"
                   : "=r"(v) : "l"(cnt) : "memory");
    } while (v < target);
  }
  __syncthreads();
}

__device__ __forceinline__ float sigmoidf_(float x) {
  return 1.0f / (1.0f + expf(-x));
}

__device__ __forceinline__ int hT_index(int j, int b) {
  return (((j >> 3) * 64 + b) << 3) + ((j & 3) << 1) + ((j >> 2) & 1);
}

#define MMA_TF32(d, a, b0, b1)                                              \
  asm volatile(                                                             \
      "mma.sync.aligned.m16n8k8.row.col.f32.tf32.tf32.f32 "                 \
      "{%0,%1,%2,%3}, {%4,%5,%6,%7}, {%8,%9}, {%0,%1,%2,%3};"               \
      : "+f"(d[0]), "+f"(d[1]), "+f"(d[2]), "+f"(d[3])                      \
      : "r"(a.x), "r"(a.y), "r"(a.z), "r"(a.w), "r"(b0), "r"(b1))

__device__ __forceinline__ void cp16(void* sdst, const void* gsrc) {
  uint32_t s = (uint32_t)__cvta_generic_to_shared(sdst);
  asm volatile("cp.async.cg.shared.global [%0], [%1], 16;" :: "r"(s), "l"(gsrc));
}
#define CP_COMMIT asm volatile("cp.async.commit_group;")
#define CP_WAIT1  asm volatile("cp.async.wait_group 1;")

// ---------------------------------------------------------------------------
// tf32 rounding pass (RNA), vectorized
// ---------------------------------------------------------------------------
__global__ void round_copy_kernel(const float4* __restrict__ src,
                                  float4* __restrict__ dst, int n4) {
  int i = blockIdx.x * blockDim.x + threadIdx.x;
  if (i < n4) {
    float4 v = src[i];
    v.x = wmma::__float_to_tf32(v.x);
    v.y = wmma::__float_to_tf32(v.y);
    v.z = wmma::__float_to_tf32(v.z);
    v.w = wmma::__float_to_tf32(v.w);
    dst[i] = v;
  }
}

__global__ void pack_h0_kernel(const float* __restrict__ h0_l) {
  int idx = blockIdx.x * blockDim.x + threadIdx.x;
  int b = idx >> 10;
  int j = idx & (kH - 1);
  g_hT[hT_index(j, b)] = wmma::__float_to_tf32(h0_l[idx]);
}

// ---------------------------------------------------------------------------
// gi GEMM (unchanged from R6): C[32768, 3072] = A @ W^T + bias
// ---------------------------------------------------------------------------
__global__ void __launch_bounds__(GI2_TH, 1) gi_kernel(
    const float* __restrict__ A,
    const float* __restrict__ W,
    const float* __restrict__ bi,
    const float* __restrict__ bh,
    float* __restrict__ C) {
  extern __shared__ float s[];
  float* As = s;
  float* Bs = s + 2 * 128 * GI_LDA;
  const int tid = threadIdx.x;
  const int lane = tid & 31;
  const int wid = tid >> 5;
  const int wm = wid >> 2;
  const int wn = wid & 3;
  const int tm = blockIdx.y * 128;
  const int tn = blockIdx.x * 128;

  float bs_[4][2];
#pragma unroll
  for (int nt = 0; nt < 4; nt++)
#pragma unroll
    for (int j = 0; j < 2; j++) {
      int n = tn + wn * 32 + nt * 8 + ((lane & 3) << 1) + j;
      bs_[nt][j] = bi[n] + (n < 2 * kH ? bh[n] : 0.0f);
    }

  float acc[4][4][4];
#pragma unroll
  for (int mt = 0; mt < 4; mt++)
#pragma unroll
    for (int nt = 0; nt < 4; nt++)
#pragma unroll
      for (int e = 0; e < 4; e++) acc[mt][nt][e] = 0.0f;

  const int lrow = tid >> 2;
  const int lc4 = tid & 3;

#pragma unroll
  for (int i = 0; i < 2; i++) {
    int row = lrow + i * 64;
    cp16(As + row * GI_LDA + lc4 * 4, A + (size_t)(tm + row) * kH + lc4 * 4);
    cp16(Bs + row * GI_LDA + lc4 * 4, W + (size_t)(tn + row) * kH + lc4 * 4);
  }
  CP_COMMIT;

  for (int kt = 0; kt < 64; kt++) {
    int cur = kt & 1;
    if (kt < 63) {
      int nxt = cur ^ 1;
      int k0 = (kt + 1) * 16;
#pragma unroll
      for (int i = 0; i < 2; i++) {
        int row = lrow + i * 64;
        cp16(As + nxt * 128 * GI_LDA + row * GI_LDA + lc4 * 4,
             A + (size_t)(tm + row) * kH + k0 + lc4 * 4);
        cp16(Bs + nxt * 128 * GI_LDA + row * GI_LDA + lc4 * 4,
             W + (size_t)(tn + row) * kH + k0 + lc4 * 4);
      }
      CP_COMMIT;
    } else {
      CP_COMMIT;
    }
    CP_WAIT1;
    __syncthreads();

    const float* Ac = As + cur * 128 * GI_LDA;
    const float* Bc = Bs + cur * 128 * GI_LDA;
#pragma unroll
    for (int ks = 0; ks < 16; ks += 8) {
      uint4 af[4];
#pragma unroll
      for (int mt = 0; mt < 4; mt++) {
        int r0 = wm * 64 + mt * 16 + (lane >> 2);
        int c = ks + (lane & 3);
        af[mt].x = __float_as_uint(Ac[r0 * GI_LDA + c]);
        af[mt].y = __float_as_uint(Ac[(r0 + 8) * GI_LDA + c]);
        af[mt].z = __float_as_uint(Ac[r0 * GI_LDA + c + 4]);
        af[mt].w = __float_as_uint(Ac[(r0 + 8) * GI_LDA + c + 4]);
      }
#pragma unroll
      for (int nt = 0; nt < 4; nt++) {
        int n0 = wn * 32 + nt * 8 + (lane >> 2);
        int k = ks + (lane & 3);
        uint32_t b0 = __float_as_uint(Bc[n0 * GI_LDA + k]);
        uint32_t b1 = __float_as_uint(Bc[n0 * GI_LDA + k + 4]);
#pragma unroll
        for (int mt = 0; mt < 4; mt++) MMA_TF32(acc[mt][nt], af[mt], b0, b1);
      }
    }
    __syncthreads();
  }

#pragma unroll
  for (int mt = 0; mt < 4; mt++)
#pragma unroll
    for (int nt = 0; nt < 4; nt++) {
      int r = tm + wm * 64 + mt * 16 + (lane >> 2);
      int n = tn + wn * 32 + nt * 8 + ((lane & 3) << 1);
      *(float2*)&C[(size_t)r * kG + n] =
          make_float2(acc[mt][nt][0] + bs_[nt][0], acc[mt][nt][1] + bs_[nt][1]);
      *(float2*)&C[(size_t)(r + 8) * kG + n] =
          make_float2(acc[mt][nt][2] + bs_[nt][0], acc[mt][nt][3] + bs_[nt][1]);
    }
}

// ---------------------------------------------------------------------------
// Recurrence: 64 CTAs x 16 warps. warp = (kg = wid&3 K-quarter,
// nq = wid>>2 batch-quarter). 192 MMAs/warp. hT via L2 (__ldcg).
// ---------------------------------------------------------------------------
__global__ void __launch_bounds__(RTH, 1) rec_kernel(
    const float* __restrict__ gi,
    const float* __restrict__ whh_l,
    const float* __restrict__ h0_l,
    float* __restrict__ seq_out,
    float* __restrict__ hfin,
    const float* __restrict__ bhh_l) {
  extern __shared__ float sm[];
  float* sA = sm;                                 // [3][KITERS][32][4]
  float* buf0 = sm + SA_FLOATS;
  float* buf1 = buf0 + NR * GHS_LD;
  const int tid = threadIdx.x;
  const int lane = tid & 31;
  const int wid = tid >> 5;
  const int j0 = blockIdx.x * HS;

  // Stage W_hh slice in A-fragment order (tf32).
  for (int idx = tid; idx < SA_FLOATS; idx += RTH) {
    int e = idx & 3;
    int ln = (idx >> 2) & 31;
    int ki = (idx >> 7) & (KITERS - 1);
    int mt = idx >> 14;
    int rr = (ln >> 2) + ((e & 1) << 3);
    int k = ki * 8 + (ln & 3) + ((e >> 1) << 2);
    float w = whh_l[(size_t)(mt * kH + j0 + rr) * kH + k];
    sA[idx] = wmma::__float_to_tf32(w);
  }

  // Epilogue ownership: jj = tid&15, br = tid>>4 (0..31), batches br, br+32.
  const int jj = tid & (HS - 1);
  const int br = tid >> 4;
  const int jg = j0 + jj;
  const float bn = bhh_l[2 * kH + jg];
  float hp[2];
#pragma unroll
  for (int q = 0; q < 2; q++)
    hp[q] = h0_l[(size_t)(br + q * 32) * kH + jg];
  __syncthreads();

  const int kg = wid & 3;            // K quarter (32 k-iters)
  const int nq = wid >> 2;           // batch quarter (16 batches)
  const int g4 = lane >> 2;
  const int l4 = lane & 3;
  const uint4* sAv = (const uint4*)sA;

  // gi prefetch for t=0
  float gir[2], giz[2], gin[2];
#pragma unroll
  for (int q = 0; q < 2; q++) {
    const float* gb = gi + ((size_t)(br + q * 32)) * kG + jg;
    gir[q] = __ldg(gb);
    giz[q] = __ldg(gb + kH);
    gin[q] = __ldg(gb + 2 * kH);
  }

  for (int t = 0; t < kT; t++) {
    const float2* hT = (const float2*)(g_hT + (size_t)(t & 1) * kB * kH);

    float acc[3][2][4];
#pragma unroll
    for (int mt = 0; mt < 3; mt++)
#pragma unroll
      for (int nt = 0; nt < 2; nt++)
#pragma unroll
        for (int e = 0; e < 4; e++) acc[mt][nt][e] = 0.0f;

#pragma unroll 4
    for (int i = 0; i < 32; i++) {
      int ki = kg * 32 + i;
      uint4 a0 = sAv[(0 * KITERS + ki) * 32 + lane];
      uint4 a1 = sAv[(1 * KITERS + ki) * 32 + lane];
      uint4 a2 = sAv[(2 * KITERS + ki) * 32 + lane];
      uint32_t bx[2], by[2];
#pragma unroll
      for (int nt = 0; nt < 2; nt++) {
        int n = nq * 16 + nt * 8 + g4;
        float2 p = __ldcg(&hT[(ki * 64 + n) * 4 + l4]);
        bx[nt] = __float_as_uint(p.x);
        by[nt] = __float_as_uint(p.y);
      }
#pragma unroll
      for (int nt = 0; nt < 2; nt++) {
        MMA_TF32(acc[0][nt], a0, bx[nt], by[nt]);
        MMA_TF32(acc[1][nt], a1, bx[nt], by[nt]);
        MMA_TF32(acc[2][nt], a2, bx[nt], by[nt]);
      }
    }

    // K-partial reduction: kg 0,1 write buffers; kg 2,3 add.
    float* buf = (kg & 1) ? buf1 : buf0;
    if (kg < 2) {
#pragma unroll
      for (int mt = 0; mt < 3; mt++)
#pragma unroll
        for (int nt = 0; nt < 2; nt++) {
          int row = mt * 16 + g4;
          int col = nq * 16 + nt * 8 + (l4 << 1);
          *(float2*)(buf + row * GHS_LD + col) =
              make_float2(acc[mt][nt][0], acc[mt][nt][1]);
          *(float2*)(buf + (row + 8) * GHS_LD + col) =
              make_float2(acc[mt][nt][2], acc[mt][nt][3]);
        }
    }
    __syncthreads();
    if (kg >= 2) {
#pragma unroll
      for (int mt = 0; mt < 3; mt++)
#pragma unroll
        for (int nt = 0; nt < 2; nt++) {
          int row = mt * 16 + g4;
          int col = nq * 16 + nt * 8 + (l4 << 1);
          float2* p0 = (float2*)(buf + row * GHS_LD + col);
          float2* p1 = (float2*)(buf + (row + 8) * GHS_LD + col);
          float2 v0 = *p0, v1 = *p1;
          v0.x += acc[mt][nt][0]; v0.y += acc[mt][nt][1];
          v1.x += acc[mt][nt][2]; v1.y += acc[mt][nt][3];
          *p0 = v0; *p1 = v1;
        }
    }
    __syncthreads();

    // Gate epilogue (gi in registers, h register-resident)
    float* hTn = g_hT + (size_t)((t + 1) & 1) * kB * kH;
#pragma unroll
    for (int q = 0; q < 2; q++) {
      int b = br + q * 32;
      float ghr = buf0[(0 * 16 + jj) * GHS_LD + b] + buf1[(0 * 16 + jj) * GHS_LD + b];
      float ghz = buf0[(1 * 16 + jj) * GHS_LD + b] + buf1[(1 * 16 + jj) * GHS_LD + b];
      float ghn = buf0[(2 * 16 + jj) * GHS_LD + b] + buf1[(2 * 16 + jj) * GHS_LD + b];
      float r = sigmoidf_(gir[q] + ghr);
      float z = sigmoidf_(giz[q] + ghz);
      float n = tanhf(gin[q] + r * (ghn + bn));
      float h = (1.0f - z) * n + z * hp[q];
      hp[q] = h;
      float hr = wmma::__float_to_tf32(h);
      seq_out[(size_t)t * kB * kH + (size_t)b * kH + jg] = hr;
      hTn[hT_index(jg, b)] = hr;
      if (t == kT - 1) hfin[(size_t)b * kH + jg] = h;
    }

    // Prefetch gi for t+1 (DRAM latency hidden under the barrier wait)
    if (t + 1 < kT) {
#pragma unroll
      for (int q = 0; q < 2; q++) {
        const float* gb = gi + ((size_t)(t + 1) * kB + br + q * 32) * kG + jg;
        gir[q] = __ldg(gb);
        giz[q] = __ldg(gb + kH);
        gin[q] = __ldg(gb + 2 * kH);
      }
    }

    grid_barrier((unsigned)t);
  }
}

// ---------------------------------------------------------------------------
// Launch
// ---------------------------------------------------------------------------
extern "C" void kernel_launch(void* const* d_in, const int* in_sizes, int n_in,
                              void* d_out, int out_size) {
  (void)in_sizes; (void)n_in; (void)out_size;
  const float* x   = (const float*)d_in[0];
  const float* h0  = (const float*)d_in[1];
  const float* wih = (const float*)d_in[2];
  const float* whh = (const float*)d_in[3];
  const float* bih = (const float*)d_in[4];
  const float* bhh = (const float*)d_in[5];
  float* out = (float*)d_out;

  float *seqA = nullptr, *seqB = nullptr, *gi = nullptr, *xr = nullptr, *wr = nullptr;
  cudaGetSymbolAddress((void**)&seqA, g_seqA);
  cudaGetSymbolAddress((void**)&seqB, g_seqB);
  cudaGetSymbolAddress((void**)&gi, g_gi);
  cudaGetSymbolAddress((void**)&xr, g_xr);
  cudaGetSymbolAddress((void**)&wr, g_wr);

  cudaFuncSetAttribute(gi_kernel, cudaFuncAttributeMaxDynamicSharedMemorySize, GI2_SMEM);
  cudaFuncSetAttribute(rec_kernel, cudaFuncAttributeMaxDynamicSharedMemorySize, REC_SMEM);

  {
    int n4x = (kT * kB * kH) / 4;
    round_copy_kernel<<<(n4x + 255) / 256, 256>>>((const float4*)x, (float4*)xr, n4x);
    int n4w = (int)(((size_t)kL * kG * kH) / 4);
    round_copy_kernel<<<(n4w + 255) / 256, 256>>>((const float4*)wih, (float4*)wr, n4w);
  }

  dim3 ggrid(kG / 128, (kT * kB) / 128);
  for (int l = 0; l < kL; l++) {
    const float* in_seq = (l == 0) ? xr : ((l & 1) ? seqA : seqB);
    float* out_seq = (l & 1) ? seqB : seqA;
    gi_kernel<<<ggrid, GI2_TH, GI2_SMEM>>>(in_seq,
                                           wr + (size_t)l * kG * kH,
                                           bih + (size_t)l * kG,
                                           bhh + (size_t)l * kG,
                                           gi);
    reset_bar_kernel<<<1, 1>>>();
    pack_h0_kernel<<<(kB * kH) / 256, 256>>>(h0 + (size_t)l * kB * kH);
    rec_kernel<<<NCTA, RTH, REC_SMEM>>>(gi,
                                        whh + (size_t)l * kG * kH,
                                        h0 + (size_t)l * kB * kH,
                                        out_seq,
                                        out + (size_t)l * kB * kH,
                                        bhh + (size_t)l * kG);
  }
}

// round 10
// speedup vs baseline: 1.2038x; 1.2038x over previous
#include <cuda_runtime.h>
#include <mma.h>
#include <cstdint>
#include <cstddef>

using namespace nvcuda;

// Problem constants
#define kT 512
#define kB 64
#define kH 1024
#define kG 3072
#define kL 4

// Recurrence config (R6 structure): 64 CTAs x 8 warps, full K per CTA.
#define HS 16
#define NR 48
#define NCTA 64
#define RTH 256
#define KITERS 128
#define GHS_LD 66
#define SA_FLOATS (3 * KITERS * 32 * 4)
#define REC_SMEM ((SA_FLOATS + 2 * NR * GHS_LD) * 4)   /* 221952 B */

// gi GEMM config: 128x128 CTA tile, 8 warps of 64x32, BK=16, double-buffered
#define GI_LDA 36
#define GI2_TH 256
#define GI2_SMEM (2 * 2 * 128 * GI_LDA * 4)   /* 73728 B */

// ---------------------------------------------------------------------------
// Scratch
// ---------------------------------------------------------------------------
__device__ float g_seqA[kT * kB * kH];
__device__ float g_seqB[kT * kB * kH];
__device__ float g_gi[(size_t)kT * kB * kG];
__device__ float g_hT[2 * kB * kH];
__device__ float g_xr[kT * kB * kH];           // tf32-rounded x
__device__ float g_wr[(size_t)kL * kG * kH];   // tf32-rounded w_ih
__device__ unsigned g_flags[NCTA * 8];         // 32B-padded per-CTA step flags

__device__ __forceinline__ float sigmoidf_(float x) {
  return 1.0f / (1.0f + expf(-x));
}

__device__ __forceinline__ int hT_index(int j, int b) {
  return (((j >> 3) * 64 + b) << 3) + ((j & 3) << 1) + ((j >> 2) & 1);
}

// Distributed-flag grid barrier. Caller guarantees a __syncthreads-ordered
// view of this CTA's stores before entry (we do the release inside).
// tid 0 publishes; tids 0..63 each poll one distinct padded flag.
__device__ __forceinline__ void grid_barrier_flags(unsigned tval) {
  __syncthreads();
  if (threadIdx.x == 0) {
    asm volatile("st.release.gpu.global.u32 [%0], %1;"
                 :: "l"(&g_flags[blockIdx.x * 8]), "r"(tval) : "memory");
  }
  if (threadIdx.x < NCTA) {
    const unsigned* f = &g_flags[threadIdx.x * 8];
    unsigned v;
    do {
      asm volatile("ld.acquire.gpu.global.u32 %0, [%1];"
                   : "=r"(v) : "l"(f) : "memory");
    } while (v < tval);
  }
  __syncthreads();
}

#define MMA_TF32(d, a, b0, b1)                                              \
  asm volatile(                                                             \
      "mma.sync.aligned.m16n8k8.row.col.f32.tf32.tf32.f32 "                 \
      "{%0,%1,%2,%3}, {%4,%5,%6,%7}, {%8,%9}, {%0,%1,%2,%3};"               \
      : "+f"(d[0]), "+f"(d[1]), "+f"(d[2]), "+f"(d[3])                      \
      : "r"(a.x), "r"(a.y), "r"(a.z), "r"(a.w), "r"(b0), "r"(b1))

__device__ __forceinline__ void cp16(void* sdst, const void* gsrc) {
  uint32_t s = (uint32_t)__cvta_generic_to_shared(sdst);
  asm volatile("cp.async.cg.shared.global [%0], [%1], 16;" :: "r"(s), "l"(gsrc));
}
#define CP_COMMIT asm volatile("cp.async.commit_group;")
#define CP_WAIT1  asm volatile("cp.async.wait_group 1;")

// ---------------------------------------------------------------------------
// tf32 rounding pass (RNA), vectorized
// ---------------------------------------------------------------------------
__global__ void round_copy_kernel(const float4* __restrict__ src,
                                  float4* __restrict__ dst, int n4) {
  int i = blockIdx.x * blockDim.x + threadIdx.x;
  if (i < n4) {
    float4 v = src[i];
    v.x = wmma::__float_to_tf32(v.x);
    v.y = wmma::__float_to_tf32(v.y);
    v.z = wmma::__float_to_tf32(v.z);
    v.w = wmma::__float_to_tf32(v.w);
    dst[i] = v;
  }
}

// pack h0 + reset barrier flags (runs before each rec launch, stream-ordered)
__global__ void pack_h0_kernel(const float* __restrict__ h0_l) {
  int idx = blockIdx.x * blockDim.x + threadIdx.x;
  if (blockIdx.x == 0 && threadIdx.x < NCTA * 8) g_flags[threadIdx.x] = 0u;
  int b = idx >> 10;
  int j = idx & (kH - 1);
  g_hT[hT_index(j, b)] = wmma::__float_to_tf32(h0_l[idx]);
}

// ---------------------------------------------------------------------------
// gi GEMM (unchanged from R6): C[32768, 3072] = A @ W^T + bias
// ---------------------------------------------------------------------------
__global__ void __launch_bounds__(GI2_TH, 1) gi_kernel(
    const float* __restrict__ A,
    const float* __restrict__ W,
    const float* __restrict__ bi,
    const float* __restrict__ bh,
    float* __restrict__ C) {
  extern __shared__ float s[];
  float* As = s;
  float* Bs = s + 2 * 128 * GI_LDA;
  const int tid = threadIdx.x;
  const int lane = tid & 31;
  const int wid = tid >> 5;
  const int wm = wid >> 2;
  const int wn = wid & 3;
  const int tm = blockIdx.y * 128;
  const int tn = blockIdx.x * 128;

  float bs_[4][2];
#pragma unroll
  for (int nt = 0; nt < 4; nt++)
#pragma unroll
    for (int j = 0; j < 2; j++) {
      int n = tn + wn * 32 + nt * 8 + ((lane & 3) << 1) + j;
      bs_[nt][j] = bi[n] + (n < 2 * kH ? bh[n] : 0.0f);
    }

  float acc[4][4][4];
#pragma unroll
  for (int mt = 0; mt < 4; mt++)
#pragma unroll
    for (int nt = 0; nt < 4; nt++)
#pragma unroll
      for (int e = 0; e < 4; e++) acc[mt][nt][e] = 0.0f;

  const int lrow = tid >> 2;
  const int lc4 = tid & 3;

#pragma unroll
  for (int i = 0; i < 2; i++) {
    int row = lrow + i * 64;
    cp16(As + row * GI_LDA + lc4 * 4, A + (size_t)(tm + row) * kH + lc4 * 4);
    cp16(Bs + row * GI_LDA + lc4 * 4, W + (size_t)(tn + row) * kH + lc4 * 4);
  }
  CP_COMMIT;

  for (int kt = 0; kt < 64; kt++) {
    int cur = kt & 1;
    if (kt < 63) {
      int nxt = cur ^ 1;
      int k0 = (kt + 1) * 16;
#pragma unroll
      for (int i = 0; i < 2; i++) {
        int row = lrow + i * 64;
        cp16(As + nxt * 128 * GI_LDA + row * GI_LDA + lc4 * 4,
             A + (size_t)(tm + row) * kH + k0 + lc4 * 4);
        cp16(Bs + nxt * 128 * GI_LDA + row * GI_LDA + lc4 * 4,
             W + (size_t)(tn + row) * kH + k0 + lc4 * 4);
      }
      CP_COMMIT;
    } else {
      CP_COMMIT;
    }
    CP_WAIT1;
    __syncthreads();

    const float* Ac = As + cur * 128 * GI_LDA;
    const float* Bc = Bs + cur * 128 * GI_LDA;
#pragma unroll
    for (int ks = 0; ks < 16; ks += 8) {
      uint4 af[4];
#pragma unroll
      for (int mt = 0; mt < 4; mt++) {
        int r0 = wm * 64 + mt * 16 + (lane >> 2);
        int c = ks + (lane & 3);
        af[mt].x = __float_as_uint(Ac[r0 * GI_LDA + c]);
        af[mt].y = __float_as_uint(Ac[(r0 + 8) * GI_LDA + c]);
        af[mt].z = __float_as_uint(Ac[r0 * GI_LDA + c + 4]);
        af[mt].w = __float_as_uint(Ac[(r0 + 8) * GI_LDA + c + 4]);
      }
#pragma unroll
      for (int nt = 0; nt < 4; nt++) {
        int n0 = wn * 32 + nt * 8 + (lane >> 2);
        int k = ks + (lane & 3);
        uint32_t b0 = __float_as_uint(Bc[n0 * GI_LDA + k]);
        uint32_t b1 = __float_as_uint(Bc[n0 * GI_LDA + k + 4]);
#pragma unroll
        for (int mt = 0; mt < 4; mt++) MMA_TF32(acc[mt][nt], af[mt], b0, b1);
      }
    }
    __syncthreads();
  }

#pragma unroll
  for (int mt = 0; mt < 4; mt++)
#pragma unroll
    for (int nt = 0; nt < 4; nt++) {
      int r = tm + wm * 64 + mt * 16 + (lane >> 2);
      int n = tn + wn * 32 + nt * 8 + ((lane & 3) << 1);
      *(float2*)&C[(size_t)r * kG + n] =
          make_float2(acc[mt][nt][0] + bs_[nt][0], acc[mt][nt][1] + bs_[nt][1]);
      *(float2*)&C[(size_t)(r + 8) * kG + n] =
          make_float2(acc[mt][nt][2] + bs_[nt][0], acc[mt][nt][3] + bs_[nt][1]);
    }
}

// ---------------------------------------------------------------------------
// Recurrence (R6 structure): 64 CTAs x 8 warps (4 K-quarters x 2 N-halves),
// 384 MMAs/warp. Distributed-flag barrier; gi t+1 prefetch before barrier.
// ---------------------------------------------------------------------------
__global__ void __launch_bounds__(RTH, 1) rec_kernel(
    const float* __restrict__ gi,
    const float* __restrict__ whh_l,
    const float* __restrict__ h0_l,
    float* __restrict__ seq_out,
    float* __restrict__ hfin,
    const float* __restrict__ bhh_l) {
  extern __shared__ float sm[];
  float* sA = sm;                                 // [3][KITERS][32][4]
  float* buf0 = sm + SA_FLOATS;
  float* buf1 = buf0 + NR * GHS_LD;
  const int tid = threadIdx.x;
  const int lane = tid & 31;
  const int wid = tid >> 5;
  const int j0 = blockIdx.x * HS;

  // Stage W_hh slice in A-fragment order (tf32).
  for (int idx = tid; idx < SA_FLOATS; idx += RTH) {
    int e = idx & 3;
    int ln = (idx >> 2) & 31;
    int ki = (idx >> 7) & (KITERS - 1);
    int mt = idx >> 14;
    int rr = (ln >> 2) + ((e & 1) << 3);
    int k = ki * 8 + (ln & 3) + ((e >> 1) << 2);
    float w = whh_l[(size_t)(mt * kH + j0 + rr) * kH + k];
    sA[idx] = wmma::__float_to_tf32(w);
  }

  // Epilogue ownership: jj = tid&15, batches (tid>>4)+{0,16,32,48}
  const int jj = tid & (HS - 1);
  const int jg = j0 + jj;
  const float bn = bhh_l[2 * kH + jg];
  float hp[4];
#pragma unroll
  for (int q = 0; q < 4; q++) {
    int b = (tid >> 4) + q * 16;
    hp[q] = h0_l[(size_t)b * kH + jg];
  }
  __syncthreads();

  const int kg = wid & 3;
  const int nhh = wid >> 2;          // N half
  const int g4 = lane >> 2;
  const int l4 = lane & 3;
  const uint4* sAv = (const uint4*)sA;

  // gi prefetch for t=0
  float gir[4], giz[4], gin[4];
#pragma unroll
  for (int q = 0; q < 4; q++) {
    int b = (tid >> 4) + q * 16;
    const float* gb = gi + ((size_t)b) * kG + jg;
    gir[q] = __ldg(gb);
    giz[q] = __ldg(gb + kH);
    gin[q] = __ldg(gb + 2 * kH);
  }

  for (int t = 0; t < kT; t++) {
    const float2* hT = (const float2*)(g_hT + (size_t)(t & 1) * kB * kH);

    float acc[3][4][4];
#pragma unroll
    for (int mt = 0; mt < 3; mt++)
#pragma unroll
      for (int nt = 0; nt < 4; nt++)
#pragma unroll
        for (int e = 0; e < 4; e++) acc[mt][nt][e] = 0.0f;

#pragma unroll 2
    for (int i = 0; i < 32; i++) {
      int ki = kg * 32 + i;
      uint4 a0 = sAv[(0 * KITERS + ki) * 32 + lane];
      uint4 a1 = sAv[(1 * KITERS + ki) * 32 + lane];
      uint4 a2 = sAv[(2 * KITERS + ki) * 32 + lane];
      uint32_t bx[4], by[4];
#pragma unroll
      for (int nt = 0; nt < 4; nt++) {
        int n = (nhh * 4 + nt) * 8 + g4;
        float2 p = hT[(ki * 64 + n) * 4 + l4];
        bx[nt] = __float_as_uint(p.x);
        by[nt] = __float_as_uint(p.y);
      }
#pragma unroll
      for (int nt = 0; nt < 4; nt++) {
        MMA_TF32(acc[0][nt], a0, bx[nt], by[nt]);
        MMA_TF32(acc[1][nt], a1, bx[nt], by[nt]);
        MMA_TF32(acc[2][nt], a2, bx[nt], by[nt]);
      }
    }

    float* buf = (kg & 1) ? buf1 : buf0;
    if (kg < 2) {
#pragma unroll
      for (int mt = 0; mt < 3; mt++)
#pragma unroll
        for (int nt = 0; nt < 4; nt++) {
          int row = mt * 16 + g4;
          int col = (nhh * 4 + nt) * 8 + (l4 << 1);
          *(float2*)(buf + row * GHS_LD + col) =
              make_float2(acc[mt][nt][0], acc[mt][nt][1]);
          *(float2*)(buf + (row + 8) * GHS_LD + col) =
              make_float2(acc[mt][nt][2], acc[mt][nt][3]);
        }
    }
    __syncthreads();
    if (kg >= 2) {
#pragma unroll
      for (int mt = 0; mt < 3; mt++)
#pragma unroll
        for (int nt = 0; nt < 4; nt++) {
          int row = mt * 16 + g4;
          int col = (nhh * 4 + nt) * 8 + (l4 << 1);
          float2* p0 = (float2*)(buf + row * GHS_LD + col);
          float2* p1 = (float2*)(buf + (row + 8) * GHS_LD + col);
          float2 v0 = *p0, v1 = *p1;
          v0.x += acc[mt][nt][0]; v0.y += acc[mt][nt][1];
          v1.x += acc[mt][nt][2]; v1.y += acc[mt][nt][3];
          *p0 = v0; *p1 = v1;
        }
    }
    __syncthreads();

    // Gate epilogue (gi in registers, h register-resident)
    float* hTn = g_hT + (size_t)((t + 1) & 1) * kB * kH;
#pragma unroll
    for (int q = 0; q < 4; q++) {
      int b = (tid >> 4) + q * 16;
      float ghr = buf0[(0 * 16 + jj) * GHS_LD + b] + buf1[(0 * 16 + jj) * GHS_LD + b];
      float ghz = buf0[(1 * 16 + jj) * GHS_LD + b] + buf1[(1 * 16 + jj) * GHS_LD + b];
      float ghn = buf0[(2 * 16 + jj) * GHS_LD + b] + buf1[(2 * 16 + jj) * GHS_LD + b];
      float r = sigmoidf_(gir[q] + ghr);
      float z = sigmoidf_(giz[q] + ghz);
      float n = tanhf(gin[q] + r * (ghn + bn));
      float h = (1.0f - z) * n + z * hp[q];
      hp[q] = h;
      float hr = wmma::__float_to_tf32(h);
      seq_out[(size_t)t * kB * kH + (size_t)b * kH + jg] = hr;
      hTn[hT_index(jg, b)] = hr;
      if (t == kT - 1) hfin[(size_t)b * kH + jg] = h;
    }

    // Prefetch gi for t+1 (DRAM latency hidden under the barrier wait)
    if (t + 1 < kT) {
#pragma unroll
      for (int q = 0; q < 4; q++) {
        int b = (tid >> 4) + q * 16;
        const float* gb = gi + ((size_t)(t + 1) * kB + b) * kG + jg;
        gir[q] = __ldg(gb);
        giz[q] = __ldg(gb + kH);
        gin[q] = __ldg(gb + 2 * kH);
      }
    }

    grid_barrier_flags((unsigned)(t + 1));
  }
}

// ---------------------------------------------------------------------------
// Launch
// ---------------------------------------------------------------------------
extern "C" void kernel_launch(void* const* d_in, const int* in_sizes, int n_in,
                              void* d_out, int out_size) {
  (void)in_sizes; (void)n_in; (void)out_size;
  const float* x   = (const float*)d_in[0];
  const float* h0  = (const float*)d_in[1];
  const float* wih = (const float*)d_in[2];
  const float* whh = (const float*)d_in[3];
  const float* bih = (const float*)d_in[4];
  const float* bhh = (const float*)d_in[5];
  float* out = (float*)d_out;

  float *seqA = nullptr, *seqB = nullptr, *gi = nullptr, *xr = nullptr, *wr = nullptr;
  cudaGetSymbolAddress((void**)&seqA, g_seqA);
  cudaGetSymbolAddress((void**)&seqB, g_seqB);
  cudaGetSymbolAddress((void**)&gi, g_gi);
  cudaGetSymbolAddress((void**)&xr, g_xr);
  cudaGetSymbolAddress((void**)&wr, g_wr);

  cudaFuncSetAttribute(gi_kernel, cudaFuncAttributeMaxDynamicSharedMemorySize, GI2_SMEM);
  cudaFuncSetAttribute(rec_kernel, cudaFuncAttributeMaxDynamicSharedMemorySize, REC_SMEM);

  {
    int n4x = (kT * kB * kH) / 4;
    round_copy_kernel<<<(n4x + 255) / 256, 256>>>((const float4*)x, (float4*)xr, n4x);
    int n4w = (int)(((size_t)kL * kG * kH) / 4);
    round_copy_kernel<<<(n4w + 255) / 256, 256>>>((const float4*)wih, (float4*)wr, n4w);
  }

  dim3 ggrid(kG / 128, (kT * kB) / 128);
  for (int l = 0; l < kL; l++) {
    const float* in_seq = (l == 0) ? xr : ((l & 1) ? seqA : seqB);
    float* out_seq = (l & 1) ? seqB : seqA;
    gi_kernel<<<ggrid, GI2_TH, GI2_SMEM>>>(in_seq,
                                           wr + (size_t)l * kG * kH,
                                           bih + (size_t)l * kG,
                                           bhh + (size_t)l * kG,
                                           gi);
    pack_h0_kernel<<<(kB * kH) / 256, 256>>>(h0 + (size_t)l * kB * kH);
    rec_kernel<<<NCTA, RTH, REC_SMEM>>>(gi,
                                        whh + (size_t)l * kG * kH,
                                        h0 + (size_t)l * kB * kH,
                                        out_seq,
                                        out + (size_t)l * kB * kH,
                                        bhh + (size_t)l * kG);
  }
}

// round 11
// speedup vs baseline: 1.5158x; 1.2592x over previous
#include <cuda_runtime.h>
#include <mma.h>
#include <cstdint>
#include <cstddef>

using namespace nvcuda;

// Problem constants
#define kT 512
#define kB 64
#define kH 1024
#define kG 3072
#define kL 4

// Recurrence config (proven R6 structure): 64 rec CTAs x 8 warps, full K.
#define HS 16
#define NR 48
#define NCTA 64
#define RTH 256
#define KITERS 128
#define GHS_LD 66
#define SA_FLOATS (3 * KITERS * 32 * 4)
#define REC_SMEM ((SA_FLOATS + 2 * NR * GHS_LD) * 4)   /* 221952 B */

// gi GEMM tile config: 128x128, 8 warps of 64x32, BK=16, double-buffered
#define GI_LDA 36
#define GI_TILES_M 256            /* 32768 / 128 */
#define GI_TILES_N 24             /* 3072 / 128 */
#define GI_TILES (GI_TILES_M * GI_TILES_N)
#define NWORK 84                  /* gi worker CTAs in fused launches */

// ---------------------------------------------------------------------------
// Scratch
// ---------------------------------------------------------------------------
__device__ float g_seqA[kT * kB * kH];
__device__ float g_seqB[kT * kB * kH];
__device__ float g_giA[(size_t)kT * kB * kG];
__device__ float g_giB[(size_t)kT * kB * kG];
__device__ float g_hT[2 * kB * kH];
__device__ float g_xr[kT * kB * kH];           // tf32-rounded x
__device__ float g_wr[(size_t)kL * kG * kH];   // tf32-rounded w_ih
__device__ unsigned g_count;
__device__ unsigned g_release;
__device__ unsigned g_ticket;

__global__ void reset_bar_kernel() { g_count = 0u; g_release = 0u; g_ticket = 0u; }

// Grid barrier over the 64 rec CTAs (original threadfence form, proven).
// Release store is st.release.gpu so gi workers can acquire-pair on it.
__device__ __forceinline__ void grid_barrier(unsigned idx) {
  __syncthreads();
  if (threadIdx.x == 0) {
    __threadfence();
    unsigned old = atomicAdd(&g_count, 1u);
    if (old == (unsigned)NCTA * (idx + 1u) - 1u) {
      __threadfence();
      asm volatile("st.release.gpu.global.u32 [%0], %1;"
                   :: "l"(&g_release), "r"(idx + 1u) : "memory");
    } else {
      while (*(volatile unsigned*)&g_release < idx + 1u) { }
    }
    __threadfence();
  }
  __syncthreads();
}

__device__ __forceinline__ float sigmoidf_(float x) {
  return 1.0f / (1.0f + expf(-x));
}

__device__ __forceinline__ int hT_index(int j, int b) {
  return (((j >> 3) * 64 + b) << 3) + ((j & 3) << 1) + ((j >> 2) & 1);
}

#define MMA_TF32(d, a, b0, b1)                                              \
  asm volatile(                                                             \
      "mma.sync.aligned.m16n8k8.row.col.f32.tf32.tf32.f32 "                 \
      "{%0,%1,%2,%3}, {%4,%5,%6,%7}, {%8,%9}, {%0,%1,%2,%3};"               \
      : "+f"(d[0]), "+f"(d[1]), "+f"(d[2]), "+f"(d[3])                      \
      : "r"(a.x), "r"(a.y), "r"(a.z), "r"(a.w), "r"(b0), "r"(b1))

__device__ __forceinline__ void cp16(void* sdst, const void* gsrc) {
  uint32_t s = (uint32_t)__cvta_generic_to_shared(sdst);
  asm volatile("cp.async.cg.shared.global [%0], [%1], 16;" :: "r"(s), "l"(gsrc));
}
#define CP_COMMIT asm volatile("cp.async.commit_group;")
#define CP_WAIT1  asm volatile("cp.async.wait_group 1;")

// ---------------------------------------------------------------------------
// tf32 rounding pass (RNA), vectorized
// ---------------------------------------------------------------------------
__global__ void round_copy_kernel(const float4* __restrict__ src,
                                  float4* __restrict__ dst, int n4) {
  int i = blockIdx.x * blockDim.x + threadIdx.x;
  if (i < n4) {
    float4 v = src[i];
    v.x = wmma::__float_to_tf32(v.x);
    v.y = wmma::__float_to_tf32(v.y);
    v.z = wmma::__float_to_tf32(v.z);
    v.w = wmma::__float_to_tf32(v.w);
    dst[i] = v;
  }
}

__global__ void pack_h0_kernel(const float* __restrict__ h0_l) {
  int idx = blockIdx.x * blockDim.x + threadIdx.x;
  int b = idx >> 10;
  int j = idx & (kH - 1);
  g_hT[hT_index(j, b)] = wmma::__float_to_tf32(h0_l[idx]);
}

// ---------------------------------------------------------------------------
// gi GEMM tile (device fn): C[tm:tm+128, tn:tn+128] = A @ W^T + bias
// ---------------------------------------------------------------------------
__device__ void gi_tile(const float* __restrict__ A,
                        const float* __restrict__ W,
                        const float* __restrict__ bi,
                        const float* __restrict__ bh,
                        float* __restrict__ C,
                        int tm, int tn, float* s) {
  float* As = s;
  float* Bs = s + 2 * 128 * GI_LDA;
  const int tid = threadIdx.x;
  const int lane = tid & 31;
  const int wid = tid >> 5;
  const int wm = wid >> 2;
  const int wn = wid & 3;

  float bs_[4][2];
#pragma unroll
  for (int nt = 0; nt < 4; nt++)
#pragma unroll
    for (int j = 0; j < 2; j++) {
      int n = tn + wn * 32 + nt * 8 + ((lane & 3) << 1) + j;
      bs_[nt][j] = bi[n] + (n < 2 * kH ? bh[n] : 0.0f);
    }

  float acc[4][4][4];
#pragma unroll
  for (int mt = 0; mt < 4; mt++)
#pragma unroll
    for (int nt = 0; nt < 4; nt++)
#pragma unroll
      for (int e = 0; e < 4; e++) acc[mt][nt][e] = 0.0f;

  const int lrow = tid >> 2;
  const int lc4 = tid & 3;

#pragma unroll
  for (int i = 0; i < 2; i++) {
    int row = lrow + i * 64;
    cp16(As + row * GI_LDA + lc4 * 4, A + (size_t)(tm + row) * kH + lc4 * 4);
    cp16(Bs + row * GI_LDA + lc4 * 4, W + (size_t)(tn + row) * kH + lc4 * 4);
  }
  CP_COMMIT;

  for (int kt = 0; kt < 64; kt++) {
    int cur = kt & 1;
    if (kt < 63) {
      int nxt = cur ^ 1;
      int k0 = (kt + 1) * 16;
#pragma unroll
      for (int i = 0; i < 2; i++) {
        int row = lrow + i * 64;
        cp16(As + nxt * 128 * GI_LDA + row * GI_LDA + lc4 * 4,
             A + (size_t)(tm + row) * kH + k0 + lc4 * 4);
        cp16(Bs + nxt * 128 * GI_LDA + row * GI_LDA + lc4 * 4,
             W + (size_t)(tn + row) * kH + k0 + lc4 * 4);
      }
      CP_COMMIT;
    } else {
      CP_COMMIT;
    }
    CP_WAIT1;
    __syncthreads();

    const float* Ac = As + cur * 128 * GI_LDA;
    const float* Bc = Bs + cur * 128 * GI_LDA;
#pragma unroll
    for (int ks = 0; ks < 16; ks += 8) {
      uint4 af[4];
#pragma unroll
      for (int mt = 0; mt < 4; mt++) {
        int r0 = wm * 64 + mt * 16 + (lane >> 2);
        int c = ks + (lane & 3);
        af[mt].x = __float_as_uint(Ac[r0 * GI_LDA + c]);
        af[mt].y = __float_as_uint(Ac[(r0 + 8) * GI_LDA + c]);
        af[mt].z = __float_as_uint(Ac[r0 * GI_LDA + c + 4]);
        af[mt].w = __float_as_uint(Ac[(r0 + 8) * GI_LDA + c + 4]);
      }
#pragma unroll
      for (int nt = 0; nt < 4; nt++) {
        int n0 = wn * 32 + nt * 8 + (lane >> 2);
        int k = ks + (lane & 3);
        uint32_t b0 = __float_as_uint(Bc[n0 * GI_LDA + k]);
        uint32_t b1 = __float_as_uint(Bc[n0 * GI_LDA + k + 4]);
#pragma unroll
        for (int mt = 0; mt < 4; mt++) MMA_TF32(acc[mt][nt], af[mt], b0, b1);
      }
    }
    __syncthreads();
  }

#pragma unroll
  for (int mt = 0; mt < 4; mt++)
#pragma unroll
    for (int nt = 0; nt < 4; nt++) {
      int r = tm + wm * 64 + mt * 16 + (lane >> 2);
      int n = tn + wn * 32 + nt * 8 + ((lane & 3) << 1);
      *(float2*)&C[(size_t)r * kG + n] =
          make_float2(acc[mt][nt][0] + bs_[nt][0], acc[mt][nt][1] + bs_[nt][1]);
      *(float2*)&C[(size_t)(r + 8) * kG + n] =
          make_float2(acc[mt][nt][2] + bs_[nt][0], acc[mt][nt][3] + bs_[nt][1]);
    }
}

// Standalone gi GEMM (layer 0 only)
__global__ void __launch_bounds__(RTH, 1) gi_kernel(
    const float* __restrict__ A, const float* __restrict__ W,
    const float* __restrict__ bi, const float* __restrict__ bh,
    float* __restrict__ C) {
  extern __shared__ float s[];
  gi_tile(A, W, bi, bh, C, blockIdx.y * 128, blockIdx.x * 128, s);
}

// ---------------------------------------------------------------------------
// Fused: bids 0..63 = recurrence (layer l); bids 64.. = gi workers for l+1.
// Workers poll g_release (rec step progress) before consuming seq_out rows.
// ---------------------------------------------------------------------------
__global__ void __launch_bounds__(RTH, 1) fused_kernel(
    const float* __restrict__ gi,     // gi for THIS layer (complete)
    const float* __restrict__ whh_l,
    const float* __restrict__ h0_l,
    float* __restrict__ seq_out,      // this layer's h sequence (tf32-rounded)
    float* __restrict__ hfin,
    const float* __restrict__ bhh_l,
    const float* __restrict__ w_next, // next layer W_ih (tf32-rounded)
    const float* __restrict__ bi_next,
    const float* __restrict__ bh_next,
    float* __restrict__ gi_next) {
  extern __shared__ float sm[];
  __shared__ int s_id;
  const int tid = threadIdx.x;

  if (blockIdx.x >= NCTA) {
    // ---------------- gi worker ----------------
    for (;;) {
      __syncthreads();
      if (tid == 0) s_id = (int)atomicAdd(&g_ticket, 1u);
      __syncthreads();
      int id = s_id;
      if (id >= GI_TILES) break;
      int mt = id / GI_TILES_N;
      int nt = id - mt * GI_TILES_N;
      unsigned need = (unsigned)(2 * mt + 2);
      if (need > (unsigned)kT) need = (unsigned)kT;
      if (tid == 0) {
        unsigned v;
        do {
          asm volatile("ld.acquire.gpu.global.u32 %0, [%1];"
                       : "=r"(v) : "l"(&g_release) : "memory");
        } while (v < need);
      }
      __syncthreads();
      gi_tile(seq_out, w_next, bi_next, bh_next, gi_next, mt * 128, nt * 128, sm);
    }
    return;
  }

  // ---------------- recurrence (proven R6 body) ----------------
  float* sA = sm;                                 // [3][KITERS][32][4]
  float* buf0 = sm + SA_FLOATS;
  float* buf1 = buf0 + NR * GHS_LD;
  const int lane = tid & 31;
  const int wid = tid >> 5;
  const int j0 = blockIdx.x * HS;

  for (int idx = tid; idx < SA_FLOATS; idx += RTH) {
    int e = idx & 3;
    int ln = (idx >> 2) & 31;
    int ki = (idx >> 7) & (KITERS - 1);
    int mt = idx >> 14;
    int rr = (ln >> 2) + ((e & 1) << 3);
    int k = ki * 8 + (ln & 3) + ((e >> 1) << 2);
    float w = whh_l[(size_t)(mt * kH + j0 + rr) * kH + k];
    sA[idx] = wmma::__float_to_tf32(w);
  }

  const int jj = tid & (HS - 1);
  const int jg = j0 + jj;
  const float bn = bhh_l[2 * kH + jg];
  float hp[4];
#pragma unroll
  for (int q = 0; q < 4; q++) {
    int b = (tid >> 4) + q * 16;
    hp[q] = h0_l[(size_t)b * kH + jg];
  }
  __syncthreads();

  const int kg = wid & 3;
  const int nhh = wid >> 2;
  const int g4 = lane >> 2;
  const int l4 = lane & 3;
  const uint4* sAv = (const uint4*)sA;

  for (int t = 0; t < kT; t++) {
    // gi prefetch (independent of h; hides DRAM latency under MMA)
    float gir[4], giz[4], gin[4];
#pragma unroll
    for (int q = 0; q < 4; q++) {
      int b = (tid >> 4) + q * 16;
      const float* gb = gi + ((size_t)t * kB + b) * kG + jg;
      gir[q] = __ldg(gb);
      giz[q] = __ldg(gb + kH);
      gin[q] = __ldg(gb + 2 * kH);
    }

    const float2* hT = (const float2*)(g_hT + (size_t)(t & 1) * kB * kH);

    float acc[3][4][4];
#pragma unroll
    for (int mt = 0; mt < 3; mt++)
#pragma unroll
      for (int nt = 0; nt < 4; nt++)
#pragma unroll
        for (int e = 0; e < 4; e++) acc[mt][nt][e] = 0.0f;

#pragma unroll 2
    for (int i = 0; i < 32; i++) {
      int ki = kg * 32 + i;
      uint4 a0 = sAv[(0 * KITERS + ki) * 32 + lane];
      uint4 a1 = sAv[(1 * KITERS + ki) * 32 + lane];
      uint4 a2 = sAv[(2 * KITERS + ki) * 32 + lane];
      uint32_t bx[4], by[4];
#pragma unroll
      for (int nt = 0; nt < 4; nt++) {
        int n = (nhh * 4 + nt) * 8 + g4;
        float2 p = hT[(ki * 64 + n) * 4 + l4];
        bx[nt] = __float_as_uint(p.x);
        by[nt] = __float_as_uint(p.y);
      }
#pragma unroll
      for (int nt = 0; nt < 4; nt++) {
        MMA_TF32(acc[0][nt], a0, bx[nt], by[nt]);
        MMA_TF32(acc[1][nt], a1, bx[nt], by[nt]);
        MMA_TF32(acc[2][nt], a2, bx[nt], by[nt]);
      }
    }

    float* buf = (kg & 1) ? buf1 : buf0;
    if (kg < 2) {
#pragma unroll
      for (int mt = 0; mt < 3; mt++)
#pragma unroll
        for (int nt = 0; nt < 4; nt++) {
          int row = mt * 16 + g4;
          int col = (nhh * 4 + nt) * 8 + (l4 << 1);
          *(float2*)(buf + row * GHS_LD + col) =
              make_float2(acc[mt][nt][0], acc[mt][nt][1]);
          *(float2*)(buf + (row + 8) * GHS_LD + col) =
              make_float2(acc[mt][nt][2], acc[mt][nt][3]);
        }
    }
    __syncthreads();
    if (kg >= 2) {
#pragma unroll
      for (int mt = 0; mt < 3; mt++)
#pragma unroll
        for (int nt = 0; nt < 4; nt++) {
          int row = mt * 16 + g4;
          int col = (nhh * 4 + nt) * 8 + (l4 << 1);
          float2* p0 = (float2*)(buf + row * GHS_LD + col);
          float2* p1 = (float2*)(buf + (row + 8) * GHS_LD + col);
          float2 v0 = *p0, v1 = *p1;
          v0.x += acc[mt][nt][0]; v0.y += acc[mt][nt][1];
          v1.x += acc[mt][nt][2]; v1.y += acc[mt][nt][3];
          *p0 = v0; *p1 = v1;
        }
    }
    __syncthreads();

    float* hTn = g_hT + (size_t)((t + 1) & 1) * kB * kH;
#pragma unroll
    for (int q = 0; q < 4; q++) {
      int b = (tid >> 4) + q * 16;
      float ghr = buf0[(0 * 16 + jj) * GHS_LD + b] + buf1[(0 * 16 + jj) * GHS_LD + b];
      float ghz = buf0[(1 * 16 + jj) * GHS_LD + b] + buf1[(1 * 16 + jj) * GHS_LD + b];
      float ghn = buf0[(2 * 16 + jj) * GHS_LD + b] + buf1[(2 * 16 + jj) * GHS_LD + b];
      float r = sigmoidf_(gir[q] + ghr);
      float z = sigmoidf_(giz[q] + ghz);
      float n = tanhf(gin[q] + r * (ghn + bn));
      float h = (1.0f - z) * n + z * hp[q];
      hp[q] = h;
      float hr = wmma::__float_to_tf32(h);
      seq_out[(size_t)t * kB * kH + (size_t)b * kH + jg] = hr;
      hTn[hT_index(jg, b)] = hr;
      if (t == kT - 1) hfin[(size_t)b * kH + jg] = h;
    }
    grid_barrier((unsigned)t);
  }
}

// ---------------------------------------------------------------------------
// Launch
// ---------------------------------------------------------------------------
extern "C" void kernel_launch(void* const* d_in, const int* in_sizes, int n_in,
                              void* d_out, int out_size) {
  (void)in_sizes; (void)n_in; (void)out_size;
  const float* x   = (const float*)d_in[0];
  const float* h0  = (const float*)d_in[1];
  const float* wih = (const float*)d_in[2];
  const float* whh = (const float*)d_in[3];
  const float* bih = (const float*)d_in[4];
  const float* bhh = (const float*)d_in[5];
  float* out = (float*)d_out;

  float *seqA, *seqB, *giA, *giB, *xr, *wr;
  cudaGetSymbolAddress((void**)&seqA, g_seqA);
  cudaGetSymbolAddress((void**)&seqB, g_seqB);
  cudaGetSymbolAddress((void**)&giA, g_giA);
  cudaGetSymbolAddress((void**)&giB, g_giB);
  cudaGetSymbolAddress((void**)&xr, g_xr);
  cudaGetSymbolAddress((void**)&wr, g_wr);

  cudaFuncSetAttribute(gi_kernel, cudaFuncAttributeMaxDynamicSharedMemorySize, REC_SMEM);
  cudaFuncSetAttribute(fused_kernel, cudaFuncAttributeMaxDynamicSharedMemorySize, REC_SMEM);

  {
    int n4x = (kT * kB * kH) / 4;
    round_copy_kernel<<<(n4x + 255) / 256, 256>>>((const float4*)x, (float4*)xr, n4x);
    int n4w = (int)(((size_t)kL * kG * kH) / 4);
    round_copy_kernel<<<(n4w + 255) / 256, 256>>>((const float4*)wih, (float4*)wr, n4w);
  }

  // Layer-0 gi (standalone)
  {
    dim3 ggrid(GI_TILES_N, GI_TILES_M);
    gi_kernel<<<ggrid, RTH, REC_SMEM>>>(xr, wr, bih, bhh, giA);
  }

  for (int l = 0; l < kL; l++) {
    float* gi_cur = (l & 1) ? giB : giA;
    float* gi_nxt = (l & 1) ? giA : giB;
    float* out_seq = (l & 1) ? seqB : seqA;
    int ln = (l + 1 < kL) ? (l + 1) : l;   // dummy ptrs for last layer
    int grid = (l + 1 < kL) ? (NCTA + NWORK) : NCTA;

    reset_bar_kernel<<<1, 1>>>();
    pack_h0_kernel<<<(kB * kH) / 256, 256>>>(h0 + (size_t)l * kB * kH);
    fused_kernel<<<grid, RTH, REC_SMEM>>>(
        gi_cur,
        whh + (size_t)l * kG * kH,
        h0 + (size_t)l * kB * kH,
        out_seq,
        out + (size_t)l * kB * kH,
        bhh + (size_t)l * kG,
        wr + (size_t)ln * kG * kH,
        bih + (size_t)ln * kG,
        bhh + (size_t)ln * kG,
        gi_nxt);
  }
}

// round 12
// speedup vs baseline: 1.5869x; 1.0469x over previous
#include <cuda_runtime.h>
#include <mma.h>
#include <cstdint>
#include <cstddef>

using namespace nvcuda;

// Problem constants
#define kT 512
#define kB 64
#define kH 1024
#define kG 3072
#define kL 4

// Recurrence config (proven R6 structure): 64 rec CTAs x 8 warps, full K.
#define HS 16
#define NR 48
#define NCTA 64
#define RTH 256
#define KITERS 128
#define GHS_LD 66
#define SA_FLOATS (3 * KITERS * 32 * 4)
#define REC_SMEM ((SA_FLOATS + 2 * NR * GHS_LD) * 4)   /* 221952 B */

// gi GEMM tile config: 128x128, 8 warps of 64x32, BK=16, double-buffered
#define GI_LDA 36
#define GI_TILES_M 256            /* 32768 / 128 */
#define GI_TILES_N 24             /* 3072 / 128 */
#define GI_TILES (GI_TILES_M * GI_TILES_N)
#define NWORK 84                  /* gi worker CTAs in fused launches */

// job mode bits
#define JOB_GATED   1             /* wait on g_release (rec step progress) */
#define JOB_ROWDONE 2             /* publish per-row completion counters  */

// ---------------------------------------------------------------------------
// Scratch
// ---------------------------------------------------------------------------
__device__ float g_seqA[kT * kB * kH];
__device__ float g_seqB[kT * kB * kH];
__device__ float g_giA[(size_t)kT * kB * kG];
__device__ float g_giB[(size_t)kT * kB * kG];
__device__ float g_hT[2 * kB * kH];
__device__ float g_xr[kT * kB * kH];           // tf32-rounded x
__device__ float g_wr[(size_t)kL * kG * kH];   // tf32-rounded w_ih
__device__ unsigned g_count;
__device__ unsigned g_release;
__device__ unsigned g_ticket;
__device__ unsigned g_rowdone[GI_TILES_M];

__global__ void reset_bar_kernel() {
  int t = threadIdx.x;
  if (t == 0) { g_count = 0u; g_release = 0u; g_ticket = 0u; }
  if (t < GI_TILES_M) g_rowdone[t] = 0u;
}

// Grid barrier over the 64 rec CTAs (proven threadfence form).
// Release store is st.release.gpu so gi workers can acquire-pair on it.
__device__ __forceinline__ void grid_barrier(unsigned idx) {
  __syncthreads();
  if (threadIdx.x == 0) {
    __threadfence();
    unsigned old = atomicAdd(&g_count, 1u);
    if (old == (unsigned)NCTA * (idx + 1u) - 1u) {
      __threadfence();
      asm volatile("st.release.gpu.global.u32 [%0], %1;"
                   :: "l"(&g_release), "r"(idx + 1u) : "memory");
    } else {
      while (*(volatile unsigned*)&g_release < idx + 1u) { }
    }
    __threadfence();
  }
  __syncthreads();
}

__device__ __forceinline__ float sigmoidf_(float x) {
  return 1.0f / (1.0f + expf(-x));
}

__device__ __forceinline__ int hT_index(int j, int b) {
  return (((j >> 3) * 64 + b) << 3) + ((j & 3) << 1) + ((j >> 2) & 1);
}

#define MMA_TF32(d, a, b0, b1)                                              \
  asm volatile(                                                             \
      "mma.sync.aligned.m16n8k8.row.col.f32.tf32.tf32.f32 "                 \
      "{%0,%1,%2,%3}, {%4,%5,%6,%7}, {%8,%9}, {%0,%1,%2,%3};"               \
      : "+f"(d[0]), "+f"(d[1]), "+f"(d[2]), "+f"(d[3])                      \
      : "r"(a.x), "r"(a.y), "r"(a.z), "r"(a.w), "r"(b0), "r"(b1))

__device__ __forceinline__ void cp16(void* sdst, const void* gsrc) {
  uint32_t s = (uint32_t)__cvta_generic_to_shared(sdst);
  asm volatile("cp.async.cg.shared.global [%0], [%1], 16;" :: "r"(s), "l"(gsrc));
}
#define CP_COMMIT asm volatile("cp.async.commit_group;")
#define CP_WAIT1  asm volatile("cp.async.wait_group 1;")

// ---------------------------------------------------------------------------
// tf32 rounding pass (RNA), vectorized
// ---------------------------------------------------------------------------
__global__ void round_copy_kernel(const float4* __restrict__ src,
                                  float4* __restrict__ dst, int n4) {
  int i = blockIdx.x * blockDim.x + threadIdx.x;
  if (i < n4) {
    float4 v = src[i];
    v.x = wmma::__float_to_tf32(v.x);
    v.y = wmma::__float_to_tf32(v.y);
    v.z = wmma::__float_to_tf32(v.z);
    v.w = wmma::__float_to_tf32(v.w);
    dst[i] = v;
  }
}

__global__ void pack_h0_kernel(const float* __restrict__ h0_l) {
  int idx = blockIdx.x * blockDim.x + threadIdx.x;
  int b = idx >> 10;
  int j = idx & (kH - 1);
  g_hT[hT_index(j, b)] = wmma::__float_to_tf32(h0_l[idx]);
}

// ---------------------------------------------------------------------------
// gi GEMM tile (device fn): C[tm:tm+128, tn:tn+128] = A @ W^T + bias
// ---------------------------------------------------------------------------
__device__ void gi_tile(const float* __restrict__ A,
                        const float* __restrict__ W,
                        const float* __restrict__ bi,
                        const float* __restrict__ bh,
                        float* __restrict__ C,
                        int tm, int tn, float* s) {
  float* As = s;
  float* Bs = s + 2 * 128 * GI_LDA;
  const int tid = threadIdx.x;
  const int lane = tid & 31;
  const int wid = tid >> 5;
  const int wm = wid >> 2;
  const int wn = wid & 3;

  float bs_[4][2];
#pragma unroll
  for (int nt = 0; nt < 4; nt++)
#pragma unroll
    for (int j = 0; j < 2; j++) {
      int n = tn + wn * 32 + nt * 8 + ((lane & 3) << 1) + j;
      bs_[nt][j] = bi[n] + (n < 2 * kH ? bh[n] : 0.0f);
    }

  float acc[4][4][4];
#pragma unroll
  for (int mt = 0; mt < 4; mt++)
#pragma unroll
    for (int nt = 0; nt < 4; nt++)
#pragma unroll
      for (int e = 0; e < 4; e++) acc[mt][nt][e] = 0.0f;

  const int lrow = tid >> 2;
  const int lc4 = tid & 3;

#pragma unroll
  for (int i = 0; i < 2; i++) {
    int row = lrow + i * 64;
    cp16(As + row * GI_LDA + lc4 * 4, A + (size_t)(tm + row) * kH + lc4 * 4);
    cp16(Bs + row * GI_LDA + lc4 * 4, W + (size_t)(tn + row) * kH + lc4 * 4);
  }
  CP_COMMIT;

  for (int kt = 0; kt < 64; kt++) {
    int cur = kt & 1;
    if (kt < 63) {
      int nxt = cur ^ 1;
      int k0 = (kt + 1) * 16;
#pragma unroll
      for (int i = 0; i < 2; i++) {
        int row = lrow + i * 64;
        cp16(As + nxt * 128 * GI_LDA + row * GI_LDA + lc4 * 4,
             A + (size_t)(tm + row) * kH + k0 + lc4 * 4);
        cp16(Bs + nxt * 128 * GI_LDA + row * GI_LDA + lc4 * 4,
             W + (size_t)(tn + row) * kH + k0 + lc4 * 4);
      }
      CP_COMMIT;
    } else {
      CP_COMMIT;
    }
    CP_WAIT1;
    __syncthreads();

    const float* Ac = As + cur * 128 * GI_LDA;
    const float* Bc = Bs + cur * 128 * GI_LDA;
#pragma unroll
    for (int ks = 0; ks < 16; ks += 8) {
      uint4 af[4];
#pragma unroll
      for (int mt = 0; mt < 4; mt++) {
        int r0 = wm * 64 + mt * 16 + (lane >> 2);
        int c = ks + (lane & 3);
        af[mt].x = __float_as_uint(Ac[r0 * GI_LDA + c]);
        af[mt].y = __float_as_uint(Ac[(r0 + 8) * GI_LDA + c]);
        af[mt].z = __float_as_uint(Ac[r0 * GI_LDA + c + 4]);
        af[mt].w = __float_as_uint(Ac[(r0 + 8) * GI_LDA + c + 4]);
      }
#pragma unroll
      for (int nt = 0; nt < 4; nt++) {
        int n0 = wn * 32 + nt * 8 + (lane >> 2);
        int k = ks + (lane & 3);
        uint32_t b0 = __float_as_uint(Bc[n0 * GI_LDA + k]);
        uint32_t b1 = __float_as_uint(Bc[n0 * GI_LDA + k + 4]);
#pragma unroll
        for (int mt = 0; mt < 4; mt++) MMA_TF32(acc[mt][nt], af[mt], b0, b1);
      }
    }
    __syncthreads();
  }

#pragma unroll
  for (int mt = 0; mt < 4; mt++)
#pragma unroll
    for (int nt = 0; nt < 4; nt++) {
      int r = tm + wm * 64 + mt * 16 + (lane >> 2);
      int n = tn + wn * 32 + nt * 8 + ((lane & 3) << 1);
      *(float2*)&C[(size_t)r * kG + n] =
          make_float2(acc[mt][nt][0] + bs_[nt][0], acc[mt][nt][1] + bs_[nt][1]);
      *(float2*)&C[(size_t)(r + 8) * kG + n] =
          make_float2(acc[mt][nt][2] + bs_[nt][0], acc[mt][nt][3] + bs_[nt][1]);
    }
}

// ---------------------------------------------------------------------------
// Fused: bids 0..63 = recurrence (layer l); bids 64.. = gi workers.
// Workers run njobs*GI_TILES tickets: job0 then job1. Jobs may be
// release-gated (consume seq_out as rec produces it) and/or publish
// per-row completion (so a gated rec can consume gi_0 incrementally).
// ---------------------------------------------------------------------------
__global__ void __launch_bounds__(RTH, 1) fused_kernel(
    const float* __restrict__ gi,     // gi for THIS layer
    const float* __restrict__ whh_l,
    const float* __restrict__ h0_l,
    float* __restrict__ seq_out,
    float* __restrict__ hfin,
    const float* __restrict__ bhh_l,
    int njobs, int rec_gated,
    const float* __restrict__ j0src, const float* __restrict__ j0w,
    const float* __restrict__ j0bi, const float* __restrict__ j0bh,
    float* __restrict__ j0dst, int j0mode,
    const float* __restrict__ j1src, const float* __restrict__ j1w,
    const float* __restrict__ j1bi, const float* __restrict__ j1bh,
    float* __restrict__ j1dst, int j1mode) {
  extern __shared__ float sm[];
  __shared__ int s_id;
  const int tid = threadIdx.x;

  if (blockIdx.x >= NCTA) {
    // ---------------- gi worker ----------------
    for (;;) {
      __syncthreads();                 // also protects smem reuse across tiles
      if (tid == 0) s_id = (int)atomicAdd(&g_ticket, 1u);
      __syncthreads();
      int id = s_id;
      if (id >= njobs * GI_TILES) break;
      int job = (id >= GI_TILES) ? 1 : 0;
      int tix = id - job * GI_TILES;
      int mt = tix / GI_TILES_N;
      int ntile = tix - mt * GI_TILES_N;
      const float* src = job ? j1src : j0src;
      const float* w   = job ? j1w   : j0w;
      const float* bi_ = job ? j1bi  : j0bi;
      const float* bh_ = job ? j1bh  : j0bh;
      float* dst       = job ? j1dst : j0dst;
      int mode         = job ? j1mode : j0mode;

      if (mode & JOB_GATED) {
        if (tid == 0) {
          unsigned need = (unsigned)(2 * mt + 2);
          if (need > (unsigned)kT) need = (unsigned)kT;
          unsigned v;
          do {
            asm volatile("ld.acquire.gpu.global.u32 %0, [%1];"
                         : "=r"(v) : "l"(&g_release) : "memory");
          } while (v < need);
        }
      }
      __syncthreads();
      gi_tile(src, w, bi_, bh_, dst, mt * 128, ntile * 128, sm);
      if (mode & JOB_ROWDONE) {
        __syncthreads();               // all threads' tile stores issued
        if (tid == 0) {
          __threadfence();
          atomicAdd(&g_rowdone[mt], 1u);
        }
      }
    }
    return;
  }

  // ---------------- recurrence (proven R6 body) ----------------
  float* sA = sm;                                 // [3][KITERS][32][4]
  float* buf0 = sm + SA_FLOATS;
  float* buf1 = buf0 + NR * GHS_LD;
  const int lane = tid & 31;
  const int wid = tid >> 5;
  const int j0 = blockIdx.x * HS;

  for (int idx = tid; idx < SA_FLOATS; idx += RTH) {
    int e = idx & 3;
    int ln = (idx >> 2) & 31;
    int ki = (idx >> 7) & (KITERS - 1);
    int mt = idx >> 14;
    int rr = (ln >> 2) + ((e & 1) << 3);
    int k = ki * 8 + (ln & 3) + ((e >> 1) << 2);
    float w = whh_l[(size_t)(mt * kH + j0 + rr) * kH + k];
    sA[idx] = wmma::__float_to_tf32(w);
  }

  const int jj = tid & (HS - 1);
  const int jg = j0 + jj;
  const float bn = bhh_l[2 * kH + jg];
  float hp[4];
#pragma unroll
  for (int q = 0; q < 4; q++) {
    int b = (tid >> 4) + q * 16;
    hp[q] = h0_l[(size_t)b * kH + jg];
  }
  __syncthreads();

  const int kg = wid & 3;
  const int nhh = wid >> 2;
  const int g4 = lane >> 2;
  const int l4 = lane & 3;
  const uint4* sAv = (const uint4*)sA;

  // Gate on gi row 0 if this layer's gi is being produced concurrently.
  if (rec_gated) {
    if (tid == 0) {
      unsigned v;
      do {
        asm volatile("ld.acquire.gpu.global.u32 %0, [%1];"
                     : "=r"(v) : "l"(&g_rowdone[0]) : "memory");
      } while (v < (unsigned)GI_TILES_N);
    }
    __syncthreads();
  }

  // gi prefetch for t=0
  float gir[4], giz[4], gin[4];
#pragma unroll
  for (int q = 0; q < 4; q++) {
    int b = (tid >> 4) + q * 16;
    const float* gb = gi + ((size_t)b) * kG + jg;
    gir[q] = __ldg(gb);
    giz[q] = __ldg(gb + kH);
    gin[q] = __ldg(gb + 2 * kH);
  }

  for (int t = 0; t < kT; t++) {
    const float2* hT = (const float2*)(g_hT + (size_t)(t & 1) * kB * kH);

    float acc[3][4][4];
#pragma unroll
    for (int mt = 0; mt < 3; mt++)
#pragma unroll
      for (int nt = 0; nt < 4; nt++)
#pragma unroll
        for (int e = 0; e < 4; e++) acc[mt][nt][e] = 0.0f;

#pragma unroll 2
    for (int i = 0; i < 32; i++) {
      int ki = kg * 32 + i;
      uint4 a0 = sAv[(0 * KITERS + ki) * 32 + lane];
      uint4 a1 = sAv[(1 * KITERS + ki) * 32 + lane];
      uint4 a2 = sAv[(2 * KITERS + ki) * 32 + lane];
      uint32_t bx[4], by[4];
#pragma unroll
      for (int nt = 0; nt < 4; nt++) {
        int n = (nhh * 4 + nt) * 8 + g4;
        float2 p = hT[(ki * 64 + n) * 4 + l4];
        bx[nt] = __float_as_uint(p.x);
        by[nt] = __float_as_uint(p.y);
      }
#pragma unroll
      for (int nt = 0; nt < 4; nt++) {
        MMA_TF32(acc[0][nt], a0, bx[nt], by[nt]);
        MMA_TF32(acc[1][nt], a1, bx[nt], by[nt]);
        MMA_TF32(acc[2][nt], a2, bx[nt], by[nt]);
      }
    }

    float* buf = (kg & 1) ? buf1 : buf0;
    if (kg < 2) {
#pragma unroll
      for (int mt = 0; mt < 3; mt++)
#pragma unroll
        for (int nt = 0; nt < 4; nt++) {
          int row = mt * 16 + g4;
          int col = (nhh * 4 + nt) * 8 + (l4 << 1);
          *(float2*)(buf + row * GHS_LD + col) =
              make_float2(acc[mt][nt][0], acc[mt][nt][1]);
          *(float2*)(buf + (row + 8) * GHS_LD + col) =
              make_float2(acc[mt][nt][2], acc[mt][nt][3]);
        }
    }
    __syncthreads();
    if (kg >= 2) {
#pragma unroll
      for (int mt = 0; mt < 3; mt++)
#pragma unroll
        for (int nt = 0; nt < 4; nt++) {
          int row = mt * 16 + g4;
          int col = (nhh * 4 + nt) * 8 + (l4 << 1);
          float2* p0 = (float2*)(buf + row * GHS_LD + col);
          float2* p1 = (float2*)(buf + (row + 8) * GHS_LD + col);
          float2 v0 = *p0, v1 = *p1;
          v0.x += acc[mt][nt][0]; v0.y += acc[mt][nt][1];
          v1.x += acc[mt][nt][2]; v1.y += acc[mt][nt][3];
          *p0 = v0; *p1 = v1;
        }
    }
    __syncthreads();

    float* hTn = g_hT + (size_t)((t + 1) & 1) * kB * kH;
#pragma unroll
    for (int q = 0; q < 4; q++) {
      int b = (tid >> 4) + q * 16;
      float ghr = buf0[(0 * 16 + jj) * GHS_LD + b] + buf1[(0 * 16 + jj) * GHS_LD + b];
      float ghz = buf0[(1 * 16 + jj) * GHS_LD + b] + buf1[(1 * 16 + jj) * GHS_LD + b];
      float ghn = buf0[(2 * 16 + jj) * GHS_LD + b] + buf1[(2 * 16 + jj) * GHS_LD + b];
      float r = sigmoidf_(gir[q] + ghr);
      float z = sigmoidf_(giz[q] + ghz);
      float n = tanhf(gin[q] + r * (ghn + bn));
      float h = (1.0f - z) * n + z * hp[q];
      hp[q] = h;
      float hr = wmma::__float_to_tf32(h);
      seq_out[(size_t)t * kB * kH + (size_t)b * kH + jg] = hr;
      hTn[hT_index(jg, b)] = hr;
      if (t == kT - 1) hfin[(size_t)b * kH + jg] = h;
    }

    // Gate + prefetch gi for t+1 (gate only on even t+1: new gi row)
    if (t + 1 < kT) {
      if (rec_gated && (((t + 1) & 1) == 0)) {
        if (tid == 0) {
          unsigned v;
          const unsigned* rd = &g_rowdone[(t + 1) >> 1];
          do {
            asm volatile("ld.acquire.gpu.global.u32 %0, [%1];"
                         : "=r"(v) : "l"(rd) : "memory");
          } while (v < (unsigned)GI_TILES_N);
        }
        __syncthreads();
      }
#pragma unroll
      for (int q = 0; q < 4; q++) {
        int b = (tid >> 4) + q * 16;
        const float* gb = gi + ((size_t)(t + 1) * kB + b) * kG + jg;
        gir[q] = __ldg(gb);
        giz[q] = __ldg(gb + kH);
        gin[q] = __ldg(gb + 2 * kH);
      }
    }
    grid_barrier((unsigned)t);
  }
}

// ---------------------------------------------------------------------------
// Launch
// ---------------------------------------------------------------------------
extern "C" void kernel_launch(void* const* d_in, const int* in_sizes, int n_in,
                              void* d_out, int out_size) {
  (void)in_sizes; (void)n_in; (void)out_size;
  const float* x   = (const float*)d_in[0];
  const float* h0  = (const float*)d_in[1];
  const float* wih = (const float*)d_in[2];
  const float* whh = (const float*)d_in[3];
  const float* bih = (const float*)d_in[4];
  const float* bhh = (const float*)d_in[5];
  float* out = (float*)d_out;

  float *seqA, *seqB, *giA, *giB, *xr, *wr;
  cudaGetSymbolAddress((void**)&seqA, g_seqA);
  cudaGetSymbolAddress((void**)&seqB, g_seqB);
  cudaGetSymbolAddress((void**)&giA, g_giA);
  cudaGetSymbolAddress((void**)&giB, g_giB);
  cudaGetSymbolAddress((void**)&xr, g_xr);
  cudaGetSymbolAddress((void**)&wr, g_wr);

  cudaFuncSetAttribute(fused_kernel, cudaFuncAttributeMaxDynamicSharedMemorySize, REC_SMEM);

  {
    int n4x = (kT * kB * kH) / 4;
    round_copy_kernel<<<(n4x + 255) / 256, 256>>>((const float4*)x, (float4*)xr, n4x);
    int n4w = (int)(((size_t)kL * kG * kH) / 4);
    round_copy_kernel<<<(n4w + 255) / 256, 256>>>((const float4*)wih, (float4*)wr, n4w);
  }

  for (int l = 0; l < kL; l++) {
    float* gi_cur = (l & 1) ? giB : giA;
    float* gi_nxt = (l & 1) ? giA : giB;
    float* out_seq = (l & 1) ? seqB : seqA;

    // Worker jobs for this launch
    int njobs, rec_gated;
    const float *j0src, *j0w, *j0bi, *j0bh, *j1src, *j1w, *j1bi, *j1bh;
    float *j0dst, *j1dst;
    int j0mode, j1mode;
    // defaults (dummies)
    j0src = j1src = xr; j0w = j1w = wr; j0bi = j1bi = bih; j0bh = j1bh = bhh;
    j0dst = j1dst = giB; j0mode = j1mode = 0;

    if (l == 0) {
      njobs = 2; rec_gated = 1;
      // job0: gi_0 = xr @ W_ih[0], ungated, publishes rowdone
      j0src = xr; j0w = wr; j0bi = bih; j0bh = bhh;
      j0dst = giA; j0mode = JOB_ROWDONE;
      // job1: gi_1 = seq_0 @ W_ih[1], release-gated
      j1src = seqA; j1w = wr + (size_t)1 * kG * kH;
      j1bi = bih + 1 * kG; j1bh = bhh + 1 * kG;
      j1dst = giB; j1mode = JOB_GATED;
    } else if (l < kL - 1) {
      njobs = 1; rec_gated = 0;
      j0src = out_seq;                       // this layer's output (in progress)
      j0w = wr + (size_t)(l + 1) * kG * kH;
      j0bi = bih + (size_t)(l + 1) * kG;
      j0bh = bhh + (size_t)(l + 1) * kG;
      j0dst = gi_nxt; j0mode = JOB_GATED;
    } else {
      njobs = 0; rec_gated = 0;
    }

    int grid = (njobs > 0) ? (NCTA + NWORK) : NCTA;

    reset_bar_kernel<<<1, 256>>>();
    pack_h0_kernel<<<(kB * kH) / 256, 256>>>(h0 + (size_t)l * kB * kH);
    fused_kernel<<<grid, RTH, REC_SMEM>>>(
        gi_cur,
        whh + (size_t)l * kG * kH,
        h0 + (size_t)l * kB * kH,
        out_seq,
        out + (size_t)l * kB * kH,
        bhh + (size_t)l * kG,
        njobs, rec_gated,
        j0src, j0w, j0bi, j0bh, j0dst, j0mode,
        j1src, j1w, j1bi, j1bh, j1dst, j1mode);
  }
}

// round 13
// speedup vs baseline: 2.0095x; 1.2663x over previous
#include <cuda_runtime.h>
#include <mma.h>
#include <cuda_fp16.h>
#include <cstdint>
#include <cstddef>

using namespace nvcuda;

// Problem constants
#define kT 512
#define kB 64
#define kH 1024
#define kG 3072
#define kL 4

// Recurrence config: 64 rec CTAs x 8 warps, full K, fp16 operands.
#define HS 16
#define NR 48
#define NCTA 64
#define RTH 256
#define KB16 64                    /* k16-blocks total (kH/16) */
#define GHS_LD 66
#define SA16_U32 (3 * KB16 * 32 * 4)          /* 24576 u32 = 98304 B */
#define REC_SMEM ((SA16_U32 + 2 * NR * GHS_LD) * 4)   /* 123648 B */

// gi GEMM tile config (unchanged, tf32): 128x128, 8 warps, BK=16
#define GI_LDA 36
#define GI_TILES_M 256
#define GI_TILES_N 24
#define GI_TILES (GI_TILES_M * GI_TILES_N)
#define NWORK 84

// job mode bits
#define JOB_GATED   1
#define JOB_ROWDONE 2

// ---------------------------------------------------------------------------
// Scratch
// ---------------------------------------------------------------------------
__device__ float g_seqA[kT * kB * kH];
__device__ float g_seqB[kT * kB * kH];
__device__ float g_giA[(size_t)kT * kB * kG];
__device__ float g_giB[(size_t)kT * kB * kG];
__device__ unsigned g_hT16[2 * KB16 * kB * 8];   // fp16 h ping-pong (half2 units)
__device__ float g_xr[kT * kB * kH];             // tf32-rounded x
__device__ float g_wr[(size_t)kL * kG * kH];     // tf32-rounded w_ih
__device__ unsigned g_count;
__device__ unsigned g_release;
__device__ unsigned g_ticket;
__device__ unsigned g_rowdone[GI_TILES_M];

__global__ void reset_bar_kernel() {
  int t = threadIdx.x;
  if (t == 0) { g_count = 0u; g_release = 0u; g_ticket = 0u; }
  if (t < GI_TILES_M) g_rowdone[t] = 0u;
}

// Grid barrier over the 64 rec CTAs (proven threadfence form).
__device__ __forceinline__ void grid_barrier(unsigned idx) {
  __syncthreads();
  if (threadIdx.x == 0) {
    __threadfence();
    unsigned old = atomicAdd(&g_count, 1u);
    if (old == (unsigned)NCTA * (idx + 1u) - 1u) {
      __threadfence();
      asm volatile("st.release.gpu.global.u32 [%0], %1;"
                   :: "l"(&g_release), "r"(idx + 1u) : "memory");
    } else {
      while (*(volatile unsigned*)&g_release < idx + 1u) { }
    }
    __threadfence();
  }
  __syncthreads();
}

__device__ __forceinline__ float sigmoidf_(float x) {
  return 1.0f / (1.0f + expf(-x));
}

// fp16 h layout: per (k16-block kb, batch b): 8 half2 units ordered
// [p0,p4,p1,p5,p2,p6,p3,p7] (p = k-pair index) so lane l4 reads its
// m16n8k16 B fragment (b0,b1) as ONE contiguous uint2 at unit 2*l4.
__device__ __forceinline__ int hT16_half_index(int j, int b) {
  int kb = j >> 4;
  int p = (j & 15) >> 1;
  int slot = ((p & 3) << 1) + (p >> 2);
  return (((kb << 6) + b) * 8 + slot) * 2 + (j & 1);
}

#define MMA_TF32(d, a, b0, b1)                                              \
  asm volatile(                                                             \
      "mma.sync.aligned.m16n8k8.row.col.f32.tf32.tf32.f32 "                 \
      "{%0,%1,%2,%3}, {%4,%5,%6,%7}, {%8,%9}, {%0,%1,%2,%3};"               \
      : "+f"(d[0]), "+f"(d[1]), "+f"(d[2]), "+f"(d[3])                      \
      : "r"(a.x), "r"(a.y), "r"(a.z), "r"(a.w), "r"(b0), "r"(b1))

#define MMA_F16(d, a, b0, b1)                                               \
  asm volatile(                                                             \
      "mma.sync.aligned.m16n8k16.row.col.f32.f16.f16.f32 "                  \
      "{%0,%1,%2,%3}, {%4,%5,%6,%7}, {%8,%9}, {%0,%1,%2,%3};"               \
      : "+f"(d[0]), "+f"(d[1]), "+f"(d[2]), "+f"(d[3])                      \
      : "r"(a.x), "r"(a.y), "r"(a.z), "r"(a.w), "r"(b0), "r"(b1))

__device__ __forceinline__ void cp16(void* sdst, const void* gsrc) {
  uint32_t s = (uint32_t)__cvta_generic_to_shared(sdst);
  asm volatile("cp.async.cg.shared.global [%0], [%1], 16;" :: "r"(s), "l"(gsrc));
}
#define CP_COMMIT asm volatile("cp.async.commit_group;")
#define CP_WAIT1  asm volatile("cp.async.wait_group 1;")

// ---------------------------------------------------------------------------
// tf32 rounding pass (RNA), vectorized
// ---------------------------------------------------------------------------
__global__ void round_copy_kernel(const float4* __restrict__ src,
                                  float4* __restrict__ dst, int n4) {
  int i = blockIdx.x * blockDim.x + threadIdx.x;
  if (i < n4) {
    float4 v = src[i];
    v.x = wmma::__float_to_tf32(v.x);
    v.y = wmma::__float_to_tf32(v.y);
    v.z = wmma::__float_to_tf32(v.z);
    v.w = wmma::__float_to_tf32(v.w);
    dst[i] = v;
  }
}

__global__ void pack_h0_kernel(const float* __restrict__ h0_l) {
  int idx = blockIdx.x * blockDim.x + threadIdx.x;
  int b = idx >> 10;
  int j = idx & (kH - 1);
  unsigned short* hT = (unsigned short*)g_hT16;
  hT[hT16_half_index(j, b)] = __half_as_ushort(__float2half_rn(h0_l[idx]));
}

// ---------------------------------------------------------------------------
// gi GEMM tile (device fn, tf32 — unchanged from R11)
// ---------------------------------------------------------------------------
__device__ void gi_tile(const float* __restrict__ A,
                        const float* __restrict__ W,
                        const float* __restrict__ bi,
                        const float* __restrict__ bh,
                        float* __restrict__ C,
                        int tm, int tn, float* s) {
  float* As = s;
  float* Bs = s + 2 * 128 * GI_LDA;
  const int tid = threadIdx.x;
  const int lane = tid & 31;
  const int wid = tid >> 5;
  const int wm = wid >> 2;
  const int wn = wid & 3;

  float bs_[4][2];
#pragma unroll
  for (int nt = 0; nt < 4; nt++)
#pragma unroll
    for (int j = 0; j < 2; j++) {
      int n = tn + wn * 32 + nt * 8 + ((lane & 3) << 1) + j;
      bs_[nt][j] = bi[n] + (n < 2 * kH ? bh[n] : 0.0f);
    }

  float acc[4][4][4];
#pragma unroll
  for (int mt = 0; mt < 4; mt++)
#pragma unroll
    for (int nt = 0; nt < 4; nt++)
#pragma unroll
      for (int e = 0; e < 4; e++) acc[mt][nt][e] = 0.0f;

  const int lrow = tid >> 2;
  const int lc4 = tid & 3;

#pragma unroll
  for (int i = 0; i < 2; i++) {
    int row = lrow + i * 64;
    cp16(As + row * GI_LDA + lc4 * 4, A + (size_t)(tm + row) * kH + lc4 * 4);
    cp16(Bs + row * GI_LDA + lc4 * 4, W + (size_t)(tn + row) * kH + lc4 * 4);
  }
  CP_COMMIT;

  for (int kt = 0; kt < 64; kt++) {
    int cur = kt & 1;
    if (kt < 63) {
      int nxt = cur ^ 1;
      int k0 = (kt + 1) * 16;
#pragma unroll
      for (int i = 0; i < 2; i++) {
        int row = lrow + i * 64;
        cp16(As + nxt * 128 * GI_LDA + row * GI_LDA + lc4 * 4,
             A + (size_t)(tm + row) * kH + k0 + lc4 * 4);
        cp16(Bs + nxt * 128 * GI_LDA + row * GI_LDA + lc4 * 4,
             W + (size_t)(tn + row) * kH + k0 + lc4 * 4);
      }
      CP_COMMIT;
    } else {
      CP_COMMIT;
    }
    CP_WAIT1;
    __syncthreads();

    const float* Ac = As + cur * 128 * GI_LDA;
    const float* Bc = Bs + cur * 128 * GI_LDA;
#pragma unroll
    for (int ks = 0; ks < 16; ks += 8) {
      uint4 af[4];
#pragma unroll
      for (int mt = 0; mt < 4; mt++) {
        int r0 = wm * 64 + mt * 16 + (lane >> 2);
        int c = ks + (lane & 3);
        af[mt].x = __float_as_uint(Ac[r0 * GI_LDA + c]);
        af[mt].y = __float_as_uint(Ac[(r0 + 8) * GI_LDA + c]);
        af[mt].z = __float_as_uint(Ac[r0 * GI_LDA + c + 4]);
        af[mt].w = __float_as_uint(Ac[(r0 + 8) * GI_LDA + c + 4]);
      }
#pragma unroll
      for (int nt = 0; nt < 4; nt++) {
        int n0 = wn * 32 + nt * 8 + (lane >> 2);
        int k = ks + (lane & 3);
        uint32_t b0 = __float_as_uint(Bc[n0 * GI_LDA + k]);
        uint32_t b1 = __float_as_uint(Bc[n0 * GI_LDA + k + 4]);
#pragma unroll
        for (int mt = 0; mt < 4; mt++) MMA_TF32(acc[mt][nt], af[mt], b0, b1);
      }
    }
    __syncthreads();
  }

#pragma unroll
  for (int mt = 0; mt < 4; mt++)
#pragma unroll
    for (int nt = 0; nt < 4; nt++) {
      int r = tm + wm * 64 + mt * 16 + (lane >> 2);
      int n = tn + wn * 32 + nt * 8 + ((lane & 3) << 1);
      *(float2*)&C[(size_t)r * kG + n] =
          make_float2(acc[mt][nt][0] + bs_[nt][0], acc[mt][nt][1] + bs_[nt][1]);
      *(float2*)&C[(size_t)(r + 8) * kG + n] =
          make_float2(acc[mt][nt][2] + bs_[nt][0], acc[mt][nt][3] + bs_[nt][1]);
    }
}

// ---------------------------------------------------------------------------
// Fused: bids 0..63 = recurrence (fp16 MMA); bids 64.. = gi workers (tf32).
// ---------------------------------------------------------------------------
__global__ void __launch_bounds__(RTH, 1) fused_kernel(
    const float* __restrict__ gi,
    const float* __restrict__ whh_l,
    const float* __restrict__ h0_l,
    float* __restrict__ seq_out,
    float* __restrict__ hfin,
    const float* __restrict__ bhh_l,
    int njobs, int rec_gated,
    const float* __restrict__ j0src, const float* __restrict__ j0w,
    const float* __restrict__ j0bi, const float* __restrict__ j0bh,
    float* __restrict__ j0dst, int j0mode,
    const float* __restrict__ j1src, const float* __restrict__ j1w,
    const float* __restrict__ j1bi, const float* __restrict__ j1bh,
    float* __restrict__ j1dst, int j1mode) {
  extern __shared__ float sm[];
  __shared__ int s_id;
  const int tid = threadIdx.x;

  if (blockIdx.x >= NCTA) {
    // ---------------- gi worker ----------------
    for (;;) {
      __syncthreads();
      if (tid == 0) s_id = (int)atomicAdd(&g_ticket, 1u);
      __syncthreads();
      int id = s_id;
      if (id >= njobs * GI_TILES) break;
      int job = (id >= GI_TILES) ? 1 : 0;
      int tix = id - job * GI_TILES;
      int mt = tix / GI_TILES_N;
      int ntile = tix - mt * GI_TILES_N;
      const float* src = job ? j1src : j0src;
      const float* w   = job ? j1w   : j0w;
      const float* bi_ = job ? j1bi  : j0bi;
      const float* bh_ = job ? j1bh  : j0bh;
      float* dst       = job ? j1dst : j0dst;
      int mode         = job ? j1mode : j0mode;

      if (mode & JOB_GATED) {
        if (tid == 0) {
          unsigned need = (unsigned)(2 * mt + 2);
          if (need > (unsigned)kT) need = (unsigned)kT;
          unsigned v;
          do {
            asm volatile("ld.acquire.gpu.global.u32 %0, [%1];"
                         : "=r"(v) : "l"(&g_release) : "memory");
          } while (v < need);
        }
      }
      __syncthreads();
      gi_tile(src, w, bi_, bh_, dst, mt * 128, ntile * 128, sm);
      if (mode & JOB_ROWDONE) {
        __syncthreads();
        if (tid == 0) {
          __threadfence();
          atomicAdd(&g_rowdone[mt], 1u);
        }
      }
    }
    return;
  }

  // ---------------- recurrence (fp16 m16n8k16) ----------------
  unsigned* sA = (unsigned*)sm;                   // [3][KB16][32 lanes][4 u32]
  float* buf0 = sm + SA16_U32;
  float* buf1 = buf0 + NR * GHS_LD;
  const int lane = tid & 31;
  const int wid = tid >> 5;
  const int j0 = blockIdx.x * HS;

  // Stage W_hh slice as fp16 in exact m16n8k16 A-fragment order.
  // e: 0=a0(gr,k0) 1=a1(gr+8,k0) 2=a2(gr,k0+8) 3=a3(gr+8,k0+8)
  for (int idx = tid; idx < SA16_U32; idx += RTH) {
    int e = idx & 3;
    int ln = (idx >> 2) & 31;
    int kb = (idx >> 7) & (KB16 - 1);
    int mt = idx >> 13;
    int rr = (ln >> 2) + ((e & 1) << 3);
    int k0 = (kb << 4) + ((ln & 3) << 1) + ((e >> 1) << 3);
    const float* wrow = whh_l + (size_t)(mt * kH + j0 + rr) * kH;
    ((__half2*)sA)[idx] = __floats2half2_rn(wrow[k0], wrow[k0 + 1]);
  }

  const int jj = tid & (HS - 1);
  const int jg = j0 + jj;
  const float bn = bhh_l[2 * kH + jg];
  float hp[4];
#pragma unroll
  for (int q = 0; q < 4; q++) {
    int b = (tid >> 4) + q * 16;
    hp[q] = h0_l[(size_t)b * kH + jg];
  }
  __syncthreads();

  const int kg = wid & 3;            // K quarter (16 k16-blocks)
  const int nhh = wid >> 2;          // N half
  const int g4 = lane >> 2;
  const int l4 = lane & 3;
  const uint4* sAv = (const uint4*)sA;

  // Gate on gi row 0 if this layer's gi is produced concurrently.
  if (rec_gated) {
    if (tid == 0) {
      unsigned v;
      do {
        asm volatile("ld.acquire.gpu.global.u32 %0, [%1];"
                     : "=r"(v) : "l"(&g_rowdone[0]) : "memory");
      } while (v < (unsigned)GI_TILES_N);
    }
    __syncthreads();
  }

  // gi prefetch for t=0
  float gir[4], giz[4], gin[4];
#pragma unroll
  for (int q = 0; q < 4; q++) {
    int b = (tid >> 4) + q * 16;
    const float* gb = gi + ((size_t)b) * kG + jg;
    gir[q] = __ldg(gb);
    giz[q] = __ldg(gb + kH);
    gin[q] = __ldg(gb + 2 * kH);
  }

  for (int t = 0; t < kT; t++) {
    const uint2* hTv = (const uint2*)(g_hT16 + (size_t)(t & 1) * (KB16 * kB * 8));

    float acc[3][4][4];
#pragma unroll
    for (int mt = 0; mt < 3; mt++)
#pragma unroll
      for (int nt = 0; nt < 4; nt++)
#pragma unroll
        for (int e = 0; e < 4; e++) acc[mt][nt][e] = 0.0f;

#pragma unroll 4
    for (int i = 0; i < 16; i++) {
      int kb = kg * 16 + i;
      uint4 a0 = sAv[(0 * KB16 + kb) * 32 + lane];
      uint4 a1 = sAv[(1 * KB16 + kb) * 32 + lane];
      uint4 a2 = sAv[(2 * KB16 + kb) * 32 + lane];
      uint32_t bx[4], by[4];
#pragma unroll
      for (int nt = 0; nt < 4; nt++) {
        int n = (nhh * 4 + nt) * 8 + g4;
        uint2 p = hTv[(kb * 64 + n) * 4 + l4];
        bx[nt] = p.x;
        by[nt] = p.y;
      }
#pragma unroll
      for (int nt = 0; nt < 4; nt++) {
        MMA_F16(acc[0][nt], a0, bx[nt], by[nt]);
        MMA_F16(acc[1][nt], a1, bx[nt], by[nt]);
        MMA_F16(acc[2][nt], a2, bx[nt], by[nt]);
      }
    }

    // K-partial reduction: kg 0,1 write buffers; kg 2,3 add.
    float* buf = (kg & 1) ? buf1 : buf0;
    if (kg < 2) {
#pragma unroll
      for (int mt = 0; mt < 3; mt++)
#pragma unroll
        for (int nt = 0; nt < 4; nt++) {
          int row = mt * 16 + g4;
          int col = (nhh * 4 + nt) * 8 + (l4 << 1);
          *(float2*)(buf + row * GHS_LD + col) =
              make_float2(acc[mt][nt][0], acc[mt][nt][1]);
          *(float2*)(buf + (row + 8) * GHS_LD + col) =
              make_float2(acc[mt][nt][2], acc[mt][nt][3]);
        }
    }
    __syncthreads();
    if (kg >= 2) {
#pragma unroll
      for (int mt = 0; mt < 3; mt++)
#pragma unroll
        for (int nt = 0; nt < 4; nt++) {
          int row = mt * 16 + g4;
          int col = (nhh * 4 + nt) * 8 + (l4 << 1);
          float2* p0 = (float2*)(buf + row * GHS_LD + col);
          float2* p1 = (float2*)(buf + (row + 8) * GHS_LD + col);
          float2 v0 = *p0, v1 = *p1;
          v0.x += acc[mt][nt][0]; v0.y += acc[mt][nt][1];
          v1.x += acc[mt][nt][2]; v1.y += acc[mt][nt][3];
          *p0 = v0; *p1 = v1;
        }
    }
    __syncthreads();

    // Gate epilogue
    unsigned short* hTn = (unsigned short*)(g_hT16 +
        (size_t)((t + 1) & 1) * (KB16 * kB * 8));
#pragma unroll
    for (int q = 0; q < 4; q++) {
      int b = (tid >> 4) + q * 16;
      float ghr = buf0[(0 * 16 + jj) * GHS_LD + b] + buf1[(0 * 16 + jj) * GHS_LD + b];
      float ghz = buf0[(1 * 16 + jj) * GHS_LD + b] + buf1[(1 * 16 + jj) * GHS_LD + b];
      float ghn = buf0[(2 * 16 + jj) * GHS_LD + b] + buf1[(2 * 16 + jj) * GHS_LD + b];
      float r = sigmoidf_(gir[q] + ghr);
      float z = sigmoidf_(giz[q] + ghz);
      float n = tanhf(gin[q] + r * (ghn + bn));
      float h = (1.0f - z) * n + z * hp[q];
      hp[q] = h;
      // tf32-rounded fp32 for next-layer gi; fp16 for the recurrence
      seq_out[(size_t)t * kB * kH + (size_t)b * kH + jg] = wmma::__float_to_tf32(h);
      hTn[hT16_half_index(jg, b)] = __half_as_ushort(__float2half_rn(h));
      if (t == kT - 1) hfin[(size_t)b * kH + jg] = h;
    }

    // Gate + prefetch gi for t+1 (gate only when a new gi row starts)
    if (t + 1 < kT) {
      if (rec_gated && (((t + 1) & 1) == 0)) {
        if (tid == 0) {
          unsigned v;
          const unsigned* rd = &g_rowdone[(t + 1) >> 1];
          do {
            asm volatile("ld.acquire.gpu.global.u32 %0, [%1];"
                         : "=r"(v) : "l"(rd) : "memory");
          } while (v < (unsigned)GI_TILES_N);
        }
        __syncthreads();
      }
#pragma unroll
      for (int q = 0; q < 4; q++) {
        int b = (tid >> 4) + q * 16;
        const float* gb = gi + ((size_t)(t + 1) * kB + b) * kG + jg;
        gir[q] = __ldg(gb);
        giz[q] = __ldg(gb + kH);
        gin[q] = __ldg(gb + 2 * kH);
      }
    }
    grid_barrier((unsigned)t);
  }
}

// ---------------------------------------------------------------------------
// Launch
// ---------------------------------------------------------------------------
extern "C" void kernel_launch(void* const* d_in, const int* in_sizes, int n_in,
                              void* d_out, int out_size) {
  (void)in_sizes; (void)n_in; (void)out_size;
  const float* x   = (const float*)d_in[0];
  const float* h0  = (const float*)d_in[1];
  const float* wih = (const float*)d_in[2];
  const float* whh = (const float*)d_in[3];
  const float* bih = (const float*)d_in[4];
  const float* bhh = (const float*)d_in[5];
  float* out = (float*)d_out;

  float *seqA, *seqB, *giA, *giB, *xr, *wr;
  cudaGetSymbolAddress((void**)&seqA, g_seqA);
  cudaGetSymbolAddress((void**)&seqB, g_seqB);
  cudaGetSymbolAddress((void**)&giA, g_giA);
  cudaGetSymbolAddress((void**)&giB, g_giB);
  cudaGetSymbolAddress((void**)&xr, g_xr);
  cudaGetSymbolAddress((void**)&wr, g_wr);

  int gi_smem = 2 * 2 * 128 * GI_LDA * 4;   // 73728
  int smem = (REC_SMEM > gi_smem) ? REC_SMEM : gi_smem;
  cudaFuncSetAttribute(fused_kernel, cudaFuncAttributeMaxDynamicSharedMemorySize, smem);

  {
    int n4x = (kT * kB * kH) / 4;
    round_copy_kernel<<<(n4x + 255) / 256, 256>>>((const float4*)x, (float4*)xr, n4x);
    int n4w = (int)(((size_t)kL * kG * kH) / 4);
    round_copy_kernel<<<(n4w + 255) / 256, 256>>>((const float4*)wih, (float4*)wr, n4w);
  }

  for (int l = 0; l < kL; l++) {
    float* gi_cur = (l & 1) ? giB : giA;
    float* gi_nxt = (l & 1) ? giA : giB;
    float* out_seq = (l & 1) ? seqB : seqA;

    int njobs, rec_gated;
    const float *j0src, *j0w, *j0bi, *j0bh, *j1src, *j1w, *j1bi, *j1bh;
    float *j0dst, *j1dst;
    int j0mode, j1mode;
    j0src = j1src = xr; j0w = j1w = wr; j0bi = j1bi = bih; j0bh = j1bh = bhh;
    j0dst = j1dst = giB; j0mode = j1mode = 0;

    if (l == 0) {
      njobs = 2; rec_gated = 1;
      j0src = xr; j0w = wr; j0bi = bih; j0bh = bhh;
      j0dst = giA; j0mode = JOB_ROWDONE;
      j1src = seqA; j1w = wr + (size_t)1 * kG * kH;
      j1bi = bih + 1 * kG; j1bh = bhh + 1 * kG;
      j1dst = giB; j1mode = JOB_GATED;
    } else if (l < kL - 1) {
      njobs = 1; rec_gated = 0;
      j0src = out_seq;
      j0w = wr + (size_t)(l + 1) * kG * kH;
      j0bi = bih + (size_t)(l + 1) * kG;
      j0bh = bhh + (size_t)(l + 1) * kG;
      j0dst = gi_nxt; j0mode = JOB_GATED;
    } else {
      njobs = 0; rec_gated = 0;
    }

    int grid = (njobs > 0) ? (NCTA + NWORK) : NCTA;

    reset_bar_kernel<<<1, 256>>>();
    pack_h0_kernel<<<(kB * kH) / 256, 256>>>(h0 + (size_t)l * kB * kH);
    fused_kernel<<<grid, RTH, smem>>>(
        gi_cur,
        whh + (size_t)l * kG * kH,
        h0 + (size_t)l * kB * kH,
        out_seq,
        out + (size_t)l * kB * kH,
        bhh + (size_t)l * kG,
        njobs, rec_gated,
        j0src, j0w, j0bi, j0bh, j0dst, j0mode,
        j1src, j1w, j1bi, j1bh, j1dst, j1mode);
  }
}

// round 14
// speedup vs baseline: 3.8560x; 1.9189x over previous
#include <cuda_runtime.h>
#include <cuda_fp16.h>
#include <cstdint>
#include <cstddef>

// Problem constants
#define kT 512
#define kB 64
#define kH 1024
#define kG 3072
#define kL 4

// Wavefront config: 128 CTAs = 4 layers x 32 slices (32 hidden units each).
// 8 warps = 4 K-groups (K=512 each of K=2048) x 2 M-halves (48 gate rows).
#define WNCTA 128
#define WTH 256
#define NSTEP (kT + kL - 1)          /* 515 */
#define RED_LD 66
#define RED_ROWS 128                  /* r(32) z(32) n_ih(32) n_hh(32) */
#define WV_SMEM ((2 * RED_ROWS * RED_LD + 192) * 4)   /* 68352 B */

// Packed weights: [cta][kg][mh][m(3)][kbl(32)][lane(32)] x uint4 (fp16 frags)
#define WP_U32 ((size_t)WNCTA * 4 * 2 * 3 * 32 * 32 * 4)   /* 12.58M u32 = 50MB */

// ---------------------------------------------------------------------------
// Scratch
// ---------------------------------------------------------------------------
__device__ unsigned g_wp_u32[WP_U32];
__device__ unsigned g_x16[(size_t)kT * 32768];   // packed fp16 x, per t: 32768 u32
__device__ unsigned g_hp16[2 * kL * 32768];      // h ping-pong per (parity, layer)
__device__ unsigned g_h016[kL * 32768];          // packed fp16 h0 per layer
__device__ unsigned g_count;
__device__ unsigned g_release;

__global__ void reset_bar_kernel() { g_count = 0u; g_release = 0u; }

// Proven threadfence grid barrier (now over 128 CTAs).
__device__ __forceinline__ void grid_barrier(unsigned idx) {
  __syncthreads();
  if (threadIdx.x == 0) {
    __threadfence();
    unsigned old = atomicAdd(&g_count, 1u);
    if (old == (unsigned)WNCTA * (idx + 1u) - 1u) {
      __threadfence();
      asm volatile("st.release.gpu.global.u32 [%0], %1;"
                   :: "l"(&g_release), "r"(idx + 1u) : "memory");
    } else {
      while (*(volatile unsigned*)&g_release < idx + 1u) { }
    }
    __threadfence();
  }
  __syncthreads();
}

__device__ __forceinline__ float sigmoidf_(float x) {
  return 1.0f / (1.0f + expf(-x));
}

#define MMA_F16(d, a, b0, b1)                                               \
  asm volatile(                                                             \
      "mma.sync.aligned.m16n8k16.row.col.f32.f16.f16.f32 "                  \
      "{%0,%1,%2,%3}, {%4,%5,%6,%7}, {%8,%9}, {%0,%1,%2,%3};"               \
      : "+f"(d[0]), "+f"(d[1]), "+f"(d[2]), "+f"(d[3])                      \
      : "r"(a.x), "r"(a.y), "r"(a.z), "r"(a.w), "r"(b0), "r"(b1))

// ---------------------------------------------------------------------------
// Packing kernels (idempotent, run every launch)
// ---------------------------------------------------------------------------
// Weights -> fragment-ordered fp16. Linear u32 index i decomposes as
// ((((((cta*4+kg)*2+mh)*3+m)*32+kbl)*32+lane)*4+e).
__global__ void pack_w_kernel(const float* __restrict__ wih,
                              const float* __restrict__ whh) {
  size_t i = (size_t)blockIdx.x * blockDim.x + threadIdx.x;
  if (i >= WP_U32) return;
  int e = (int)(i & 3);
  int lane = (int)((i >> 2) & 31);
  int kbl = (int)((i >> 7) & 31);
  int rem = (int)(i >> 12);
  int m = rem % 3; rem /= 3;
  int mh = rem & 1;
  int kg = (rem >> 1) & 3;
  int cta = rem >> 3;
  int layer = cta >> 5, slice = cta & 31;
  int mtp = mh * 3 + m;
  int gate = mtp >> 1;
  int rr = ((mtp & 1) << 4) + (lane >> 2) + ((e & 1) << 3);
  int k = (kg * 32 + kbl) * 16 + ((lane & 3) << 1) + ((e >> 1) << 3);
  int row = gate * kH + slice * 32 + rr;
  const float* W = (k < kH) ? (wih + (size_t)layer * kG * kH)
                            : (whh + (size_t)layer * kG * kH);
  int kk = k & (kH - 1);
  __half2 h2 = __floats2half2_rn(W[(size_t)row * kH + kk],
                                 W[(size_t)row * kH + kk + 1]);
  g_wp_u32[i] = *(unsigned*)&h2;
}

// x -> packed fp16 B-operand layout (same slot scheme as R12 hT16).
__global__ void pack_x_kernel(const float* __restrict__ x) {
  size_t i = (size_t)blockIdx.x * blockDim.x + threadIdx.x;  // < kT*kB*512
  int t = (int)(i >> 15);
  int r = (int)(i & 32767);
  int b = r >> 9;
  int jp = r & 511;
  int j = jp << 1;
  const float* src = x + (size_t)t * kB * kH + (size_t)b * kH + j;
  int kb = j >> 4;
  int p = (j >> 1) & 7;
  int slot = ((p & 3) << 1) + (p >> 2);
  __half2 h2 = __floats2half2_rn(src[0], src[1]);
  g_x16[(size_t)t * 32768 + ((size_t)(kb * 64 + b)) * 8 + slot] = *(unsigned*)&h2;
}

// h0 (all layers) -> packed fp16
__global__ void pack_h0_kernel(const float* __restrict__ h0) {
  int i = blockIdx.x * blockDim.x + threadIdx.x;   // < kL*32768
  int layer = i >> 15;
  int r = i & 32767;
  int b = r >> 9;
  int jp = r & 511;
  int j = jp << 1;
  const float* src = h0 + (size_t)layer * kB * kH + (size_t)b * kH + j;
  int kb = j >> 4;
  int p = (j >> 1) & 7;
  int slot = ((p & 3) << 1) + (p >> 2);
  __half2 h2 = __floats2half2_rn(src[0], src[1]);
  g_h016[layer * 32768 + (kb * 64 + b) * 8 + slot] = *(unsigned*)&h2;
}

// ---------------------------------------------------------------------------
// Wavefront kernel: 128 CTAs, 515 steps. Per active step, CTA (layer, slice)
// computes gates[128 partial rows, 64] = W_frag @ [h_{l-1}[t] ; h_l[t-1]]
// with weights streamed from L2 (LDG.128, fragment-packed) and h from the
// packed fp16 ping-pong. n-gate ih/hh parts kept separate via the K-split.
// ---------------------------------------------------------------------------
__global__ void __launch_bounds__(WTH, 1) wave_kernel(
    const float* __restrict__ h0f,
    const float* __restrict__ bih,
    const float* __restrict__ bhh,
    float* __restrict__ out) {
  extern __shared__ float sm[];
  float* red0 = sm;                          // [128][RED_LD]
  float* red1 = sm + RED_ROWS * RED_LD;
  float* sbias = sm + 2 * RED_ROWS * RED_LD; // [6][32]
  const int tid = threadIdx.x;
  const int lane = tid & 31;
  const int wid = tid >> 5;
  const int layer = blockIdx.x >> 5;
  const int slice = blockIdx.x & 31;
  const int j0 = slice * 32;

  // Stage biases: [bi_r, bi_z, bi_n, bh_r, bh_z, bh_n][jj]
  for (int i = tid; i < 192; i += WTH) {
    int g = i >> 5, jj = i & 31;
    sbias[i] = ((g < 3) ? bih : bhh)[(size_t)layer * kG + (g % 3) * kH + j0 + jj];
  }

  // Register-resident h_prev: thread owns 8 (jj, b) outputs.
  float hp[8];
#pragma unroll
  for (int k = 0; k < 8; k++) {
    int e = tid + k * WTH;
    int jj = e >> 6, b = e & 63;
    hp[k] = h0f[(size_t)layer * kB * kH + (size_t)b * kH + j0 + jj];
  }
  __syncthreads();

  const int kg = wid >> 1;          // K group: 0,1 = ih half; 2,3 = hh half
  const int mh = wid & 1;           // M half (3 of 6 m-tiles)
  const int g4 = lane >> 2;
  const int l4 = lane & 3;
  const uint4* wpw = (const uint4*)g_wp_u32 +
      ((((size_t)blockIdx.x * 4 + kg) * 2 + mh) * 3 * 32 * 32);

  for (int s = 0; s < NSTEP; s++) {
    int t = s - layer;
    if (t >= 0 && t < kT) {
      // B-operand source for this warp's K half
      const uint2* bsrc;
      if (kg < 2) {
        bsrc = (layer == 0)
            ? (const uint2*)(g_x16 + (size_t)t * 32768)
            : (const uint2*)(g_hp16 + (size_t)(((s - 1) & 1) * kL + (layer - 1)) * 32768);
      } else {
        bsrc = (t == 0)
            ? (const uint2*)(g_h016 + (size_t)layer * 32768)
            : (const uint2*)(g_hp16 + (size_t)(((s - 1) & 1) * kL + layer) * 32768);
      }

      float acc[3][8][4];
#pragma unroll
      for (int m = 0; m < 3; m++)
#pragma unroll
        for (int nt = 0; nt < 8; nt++)
#pragma unroll
          for (int e = 0; e < 4; e++) acc[m][nt][e] = 0.0f;

#pragma unroll 4
      for (int kbl = 0; kbl < 32; kbl++) {
        int kb_src = (kg * 32 + kbl) & 63;
        uint4 a0 = wpw[(0 * 32 + kbl) * 32 + lane];
        uint4 a1 = wpw[(1 * 32 + kbl) * 32 + lane];
        uint4 a2 = wpw[(2 * 32 + kbl) * 32 + lane];
        uint2 bf[8];
#pragma unroll
        for (int nt = 0; nt < 8; nt++)
          bf[nt] = bsrc[((size_t)(kb_src * 64 + nt * 8 + g4)) * 4 + l4];
#pragma unroll
        for (int nt = 0; nt < 8; nt++) {
          MMA_F16(acc[0][nt], a0, bf[nt].x, bf[nt].y);
          MMA_F16(acc[1][nt], a1, bf[nt].x, bf[nt].y);
          MMA_F16(acc[2][nt], a2, bf[nt].x, bf[nt].y);
        }
      }

      // Reduce across 4 K-groups into 2 buffers.
      // Rows: r 0-31, z 32-63, n_ih 64-95, n_hh 96-127.
      float* buf = (kg & 1) ? red1 : red0;
      if (kg < 2) {
        // phase1: write all rows (r,z direct; m-tiles 4,5 are n_ih at 64+)
#pragma unroll
        for (int m = 0; m < 3; m++) {
          int mtp = mh * 3 + m;
          int base = (mtp < 4) ? mtp * 16 : 64 + (mtp - 4) * 16;
          int row = base + g4;
#pragma unroll
          for (int nt = 0; nt < 8; nt++) {
            int col = nt * 8 + (l4 << 1);
            *(float2*)(buf + row * RED_LD + col) =
                make_float2(acc[m][nt][0], acc[m][nt][1]);
            *(float2*)(buf + (row + 8) * RED_LD + col) =
                make_float2(acc[m][nt][2], acc[m][nt][3]);
          }
        }
      } else if (mh == 1) {
        // phase1: hh warps write n_hh rows (96+) only (disjoint)
#pragma unroll
        for (int m = 1; m < 3; m++) {
          int base = 96 + (3 + m - 4) * 16;
          int row = base + g4;
#pragma unroll
          for (int nt = 0; nt < 8; nt++) {
            int col = nt * 8 + (l4 << 1);
            *(float2*)(buf + row * RED_LD + col) =
                make_float2(acc[m][nt][0], acc[m][nt][1]);
            *(float2*)(buf + (row + 8) * RED_LD + col) =
                make_float2(acc[m][nt][2], acc[m][nt][3]);
          }
        }
      }
      __syncthreads();
      if (kg >= 2) {
        // phase2: hh warps add their r,z partials
#pragma unroll
        for (int m = 0; m < 3; m++) {
          int mtp = mh * 3 + m;
          if (mtp < 4) {
            int row = mtp * 16 + g4;
#pragma unroll
            for (int nt = 0; nt < 8; nt++) {
              int col = nt * 8 + (l4 << 1);
              float2* p0 = (float2*)(buf + row * RED_LD + col);
              float2* p1 = (float2*)(buf + (row + 8) * RED_LD + col);
              float2 v0 = *p0, v1 = *p1;
              v0.x += acc[m][nt][0]; v0.y += acc[m][nt][1];
              v1.x += acc[m][nt][2]; v1.y += acc[m][nt][3];
              *p0 = v0; *p1 = v1;
            }
          }
        }
      }
      __syncthreads();

      // Gate epilogue + publish
      unsigned short* hout = (unsigned short*)(g_hp16 +
          (size_t)((s & 1) * kL + layer) * 32768);
#pragma unroll
      for (int k = 0; k < 8; k++) {
        int e = tid + k * WTH;
        int jj = e >> 6, b = e & 63;
        float vr   = red0[jj * RED_LD + b]        + red1[jj * RED_LD + b];
        float vz   = red0[(32 + jj) * RED_LD + b] + red1[(32 + jj) * RED_LD + b];
        float vnih = red0[(64 + jj) * RED_LD + b] + red1[(64 + jj) * RED_LD + b];
        float vnhh = red0[(96 + jj) * RED_LD + b] + red1[(96 + jj) * RED_LD + b];
        float r = sigmoidf_(vr + sbias[jj] + sbias[96 + jj]);
        float z = sigmoidf_(vz + sbias[32 + jj] + sbias[128 + jj]);
        float n = tanhf(vnih + sbias[64 + jj] + r * (vnhh + sbias[160 + jj]));
        float h = (1.0f - z) * n + z * hp[k];
        hp[k] = h;
        int jg = j0 + jj;
        int p = (jg & 15) >> 1;
        int slot = ((p & 3) << 1) + (p >> 2);
        hout[((((jg >> 4) * 64 + b)) * 8 + slot) * 2 + (jg & 1)] =
            __half_as_ushort(__float2half_rn(h));
        if (t == kT - 1)
          out[(size_t)layer * kB * kH + (size_t)b * kH + jg] = h;
      }
    }
    grid_barrier((unsigned)s);
  }
}

// ---------------------------------------------------------------------------
// Launch
// ---------------------------------------------------------------------------
extern "C" void kernel_launch(void* const* d_in, const int* in_sizes, int n_in,
                              void* d_out, int out_size) {
  (void)in_sizes; (void)n_in; (void)out_size;
  const float* x   = (const float*)d_in[0];
  const float* h0  = (const float*)d_in[1];
  const float* wih = (const float*)d_in[2];
  const float* whh = (const float*)d_in[3];
  const float* bih = (const float*)d_in[4];
  const float* bhh = (const float*)d_in[5];
  float* out = (float*)d_out;

  cudaFuncSetAttribute(wave_kernel, cudaFuncAttributeMaxDynamicSharedMemorySize,
                       WV_SMEM);

  // Idempotent packing passes
  {
    size_t nw = WP_U32;
    pack_w_kernel<<<(unsigned)((nw + 255) / 256), 256>>>(wih, whh);
    size_t nx = (size_t)kT * kB * 512;
    pack_x_kernel<<<(unsigned)((nx + 255) / 256), 256>>>(x);
    pack_h0_kernel<<<(kL * 32768) / 256, 256>>>(h0);
    reset_bar_kernel<<<1, 1>>>();
  }

  wave_kernel<<<WNCTA, WTH, WV_SMEM>>>(h0, bih, bhh, out);
}